// round 12
// baseline (speedup 1.0000x reference)
#include <cuda_runtime.h>
#include <math.h>
#include <stdint.h>

#define BATCH 16
#define TT 64
#define NSAMP 1024

__device__ float d_y1[NSAMP * 32 * 32 * 32];
__device__ float d_y2[NSAMP * 64 * 16 * 16];
__device__ float d_y3[NSAMP * 128 * 8 * 8];
__device__ float d_y4[NSAMP * 256 * 4 * 4];
__device__ float d_feats[NSAMP * 256];
__device__ float d_fpart[NSAMP * 1024];
__device__ float d_stats[4][NSAMP][2];

#define OUT_PRIOR 0
#define OUT_POST  1048576
#define OUT_H     2097152
#define OUT_Z     2228224

__global__ void init_kernel() {
    int i = blockIdx.x * 256 + threadIdx.x;
    if (i < 4 * NSAMP * 2) ((float*)d_stats)[i] = 0.f;
}

// ---------------- conv1: 3ch 64x64 -> 32ch 32x32 (PW=68, weight-swizzled) ----------------
__global__ __launch_bounds__(256) void conv1_kernel(const float* __restrict__ x,
                                                    const float* __restrict__ w,
                                                    const float* __restrict__ bias) {
    extern __shared__ float sm[];
    float* in_s = sm;                 // 3*66*68
    float* w_s  = sm + 3 * 66 * 68;   // 32*48
    int n = blockIdx.x, tid = threadIdx.x;
    for (int i = tid; i < 3 * 66 * 68; i += 256) in_s[i] = 0.f;
    for (int i = tid; i < 32 * 48; i += 256) {
        int oc = i / 48, r = i % 48;
        int pos = oc * 48 + (r & ~15) + ((((r >> 2) ^ (oc >> 2)) & 3) << 2) + (r & 3);
        w_s[pos] = w[i];
    }
    __syncthreads();
    for (int i = tid; i < 3 * 64 * 64; i += 256) {
        int c = i >> 12, r = i & 4095, y = r >> 6, xx = r & 63;
        in_s[(c * 66 + y + 1) * 68 + xx + 1] = x[(size_t)n * 12288 + i];
    }
    __syncthreads();
    float s_sum = 0.f, s_sq = 0.f;
    int ocg = tid & 7, qb = tid >> 3;
    int swz = ocg & 3;
#pragma unroll 1
    for (int qi = 0; qi < 8; qi++) {
        int q = qb + qi * 32;
        int oy = q >> 3, ox0 = (q & 7) << 2;
        float acc[16];
#pragma unroll
        for (int i = 0; i < 16; i++) acc[i] = 0.f;
#pragma unroll
        for (int c = 0; c < 3; c++)
#pragma unroll
            for (int ky = 0; ky < 4; ky++) {
                const float4* xp = (const float4*)(in_s + (c * 66 + oy * 2 + ky) * 68 + ox0 * 2);
                float xr[12];
                *(float4*)&xr[0] = xp[0];
                *(float4*)&xr[4] = xp[1];
                *(float4*)&xr[8] = xp[2];
                int kys = (ky ^ swz) << 2;
#pragma unroll
                for (int o = 0; o < 4; o++) {
                    float4 wv = *(const float4*)(w_s + (ocg * 4 + o) * 48 + c * 16 + kys);
#pragma unroll
                    for (int m = 0; m < 4; m++)
                        acc[o * 4 + m] += wv.x * xr[2 * m] + wv.y * xr[2 * m + 1]
                                        + wv.z * xr[2 * m + 2] + wv.w * xr[2 * m + 3];
                }
            }
#pragma unroll
        for (int o = 0; o < 4; o++) {
            int oc = ocg * 4 + o;
            float bv = __ldg(&bias[oc]);
#pragma unroll
            for (int m = 0; m < 4; m++) {
                float v = acc[o * 4 + m] + bv;
                d_y1[(((size_t)n * 32 + oc) * 32 + oy) * 32 + ox0 + m] = v;
                s_sum += v; s_sq += v * v;
            }
        }
    }
    for (int off = 16; off; off >>= 1) {
        s_sum += __shfl_down_sync(0xffffffffu, s_sum, off);
        s_sq  += __shfl_down_sync(0xffffffffu, s_sq, off);
    }
    if ((tid & 31) == 0) {
        atomicAdd(&d_stats[0][n][0], s_sum);
        atomicAdd(&d_stats[0][n][1], s_sq);
    }
}

// ---------------- generic conv (stages 1..3): PX-wide register tiles ----------------
template <int STAGE> __device__ __forceinline__ const float* conv_in() {
    if constexpr (STAGE == 1) return d_y1; else if constexpr (STAGE == 2) return d_y2; else return d_y3;
}
template <int STAGE> __device__ __forceinline__ float* conv_out() {
    if constexpr (STAGE == 1) return d_y2; else if constexpr (STAGE == 2) return d_y3; else return d_y4;
}

template <int CIN, int H, int COUT, int OCB, int PX, int NS, int PW, int STAGE>
__global__ __launch_bounds__(256) void conv_kernel(const float* __restrict__ w,
                                                   const float* __restrict__ bias) {
    constexpr int W = H, OH = H / 2, OW = H / 2, PH = H + 2;
    constexpr int TO = 32 / PX;
    constexpr int OCG = OCB / TO;
    constexpr int QN = OH * OW / PX;
    constexpr int CHSTRIDE = 8 * PH * PW + 8;
    constexpr int WCH = OCB * 8 * 16;
    constexpr int NROWS = NS * 8 * PH;
    extern __shared__ float sm[];
    float* w_s = sm;
    float* in_s = sm + WCH;
    const float* xin = conv_in<STAGE>();
    float* yout = conv_out<STAGE>();
    int tid = threadIdx.x;
    int n0 = blockIdx.x * NS;
    int oc0 = blockIdx.y * OCB;

    int smp = tid / (OCG * QN);
    int rem = tid % (OCG * QN);
    int ocg = rem % OCG;
    int qn = rem / OCG;
    int oy = qn / (OW / PX);
    int ox0 = (qn % (OW / PX)) * PX;
    int n = n0 + smp;

    float acc[32];
#pragma unroll
    for (int i = 0; i < 32; i++) acc[i] = 0.f;

    for (int icb = 0; icb < CIN / 8; icb++) {
        __syncthreads();
        for (int i = tid; i < WCH; i += 256) {
            int r = i & 127;
            int pos = (i & ~15) | ((((i >> 2) ^ (i >> 9)) & 3) << 2) | (i & 3);
            w_s[pos] = w[(size_t)(oc0 + (i >> 7)) * CIN * 16 + icb * 128 + r];
        }
        for (int r = tid; r < NROWS; r += 256) {
            int s = r / (8 * PH);
            int rem2 = r - s * (8 * PH);
            int c = rem2 / PH;
            int y = rem2 - c * PH;
            float* base = in_s + s * CHSTRIDE + (c * PH + y) * PW;
            if (y == 0 || y == PH - 1) {
#pragma unroll
                for (int j = 0; j < PW; j++) base[j] = 0.f;
            } else {
                base[0] = 0.f;
#pragma unroll
                for (int j = W + 1; j < PW; j++) base[j] = 0.f;
                const float4* src = (const float4*)(xin +
                    (((size_t)(n0 + s) * CIN + icb * 8 + c) * H + (y - 1)) * W);
#pragma unroll
                for (int j = 0; j < W / 4; j++) {
                    float4 v = __ldg(src + j);
                    base[1 + 4 * j] = v.x; base[2 + 4 * j] = v.y;
                    base[3 + 4 * j] = v.z; base[4 + 4 * j] = v.w;
                }
            }
        }
        __syncthreads();
#pragma unroll
        for (int icl = 0; icl < 8; icl++) {
            const float* inc = in_s + smp * CHSTRIDE + icl * PH * PW;
            const float* wb = w_s + icl * 16;
#pragma unroll
            for (int ky = 0; ky < 4; ky++) {
                const float4* xp = (const float4*)(inc + (oy * 2 + ky) * PW + ox0 * 2);
                float xr[2 * PX + 4];
#pragma unroll
                for (int f = 0; f < PX / 2 + 1; f++) *(float4*)&xr[4 * f] = xp[f];
#pragma unroll
                for (int o = 0; o < TO; o++) {
                    int ol = ocg * TO + o;
                    float4 wv = *(const float4*)(wb + ol * 128 + ((ky ^ ((ol >> 2) & 3)) << 2));
#pragma unroll
                    for (int m = 0; m < PX; m++)
                        acc[o * PX + m] += wv.x * xr[2 * m] + wv.y * xr[2 * m + 1]
                                         + wv.z * xr[2 * m + 2] + wv.w * xr[2 * m + 3];
                }
            }
        }
    }
    float s_sum = 0.f, s_sq = 0.f;
#pragma unroll
    for (int o = 0; o < TO; o++) {
        int oc = oc0 + ocg * TO + o;
        float bv = __ldg(&bias[oc]);
#pragma unroll
        for (int m = 0; m < PX; m++) {
            float v = acc[o * PX + m] + bv;
            yout[(((size_t)n * COUT + oc) * OH + oy) * OW + ox0 + m] = v;
            s_sum += v; s_sq += v * v;
        }
    }
    constexpr int RW = (OCG * QN >= 32) ? 32 : (OCG * QN);
    for (int off = RW / 2; off; off >>= 1) {
        s_sum += __shfl_down_sync(0xffffffffu, s_sum, off, RW);
        s_sq  += __shfl_down_sync(0xffffffffu, s_sq, off, RW);
    }
    if ((tid % RW) == 0) {
        atomicAdd(&d_stats[STAGE][n][0], s_sum);
        atomicAdd(&d_stats[STAGE][n][1], s_sq);
    }
}

// ---------------- LayerNorm + SiLU (vectorized) ----------------
template <int CHW, int STAGE>
__global__ void ln_silu_kernel(const float* __restrict__ g, const float* __restrict__ bp) {
    float* y;
    if constexpr (STAGE == 0) y = d_y1;
    else if constexpr (STAGE == 1) y = d_y2;
    else if constexpr (STAGE == 2) y = d_y3;
    else y = d_y4;
    int n = blockIdx.x;
    float mean = d_stats[STAGE][n][0] * (1.f / CHW);
    float var = d_stats[STAGE][n][1] * (1.f / CHW) - mean * mean;
    float inv = rsqrtf(var + 1e-5f);
    float4* yp = (float4*)(y + (size_t)n * CHW);
    const float4* gp = (const float4*)g;
    const float4* bpp = (const float4*)bp;
    for (int i = threadIdx.x; i < CHW / 4; i += blockDim.x) {
        float4 v4 = yp[i], g4 = __ldg(gp + i), b4 = __ldg(bpp + i);
        float a0 = (v4.x - mean) * inv * g4.x + b4.x;
        float a1 = (v4.y - mean) * inv * g4.y + b4.y;
        float a2 = (v4.z - mean) * inv * g4.z + b4.z;
        float a3 = (v4.w - mean) * inv * g4.w + b4.w;
        v4.x = a0 / (1.f + __expf(-a0));
        v4.y = a1 / (1.f + __expf(-a1));
        v4.z = a2 / (1.f + __expf(-a2));
        v4.w = a3 / (1.f + __expf(-a3));
        yp[i] = v4;
    }
}

// ---------------- SGEMM: C[M,N] = A[M,K] * B[N,:K]^T + bias ----------------
// WHICH=0: A=d_y4 -> C=d_feats. WHICH=1: A=d_feats -> C=d_fpart. WHICH=2: ext ptrs.
// __device__ globals MUST be resolved in device code (host-side symbol refs
// give the host shadow address — silently "works" via ATS on GB300).
template <int KK, int LDB, int WHICH>
__global__ __launch_bounds__(256) void gemm_kernel(const float* __restrict__ Bmat,
                                                   const float* __restrict__ bias,
                                                   const float* __restrict__ Aext,
                                                   float* __restrict__ Cext) {
    const float* A = (WHICH == 0) ? d_y4 : (WHICH == 1) ? d_feats : Aext;
    float* C = (WHICH == 0) ? d_feats : (WHICH == 1) ? d_fpart : Cext;
    const int ldc = gridDim.y * 64;
    __shared__ float As[16][68];
    __shared__ float Bs[16][68];
    int m0 = blockIdx.x * 64, n0 = blockIdx.y * 64;
    int tid = threadIdx.x;
    int tx = tid % 16, ty = tid / 16;
    float acc[16];
#pragma unroll
    for (int i = 0; i < 16; i++) acc[i] = 0.f;
    for (int k0 = 0; k0 < KK; k0 += 16) {
#pragma unroll
        for (int e = 0; e < 4; e++) {
            int f = tid + e * 256;
            int m = f >> 4, k = f & 15;
            As[k][m] = A[(size_t)(m0 + m) * KK + k0 + k];
            Bs[k][m] = Bmat[(size_t)(n0 + m) * LDB + k0 + k];
        }
        __syncthreads();
#pragma unroll
        for (int k = 0; k < 16; k++) {
            float4 a4 = *(const float4*)&As[k][ty * 4];
            float4 b4 = *(const float4*)&Bs[k][tx * 4];
            acc[0]  += a4.x * b4.x; acc[1]  += a4.x * b4.y; acc[2]  += a4.x * b4.z; acc[3]  += a4.x * b4.w;
            acc[4]  += a4.y * b4.x; acc[5]  += a4.y * b4.y; acc[6]  += a4.y * b4.z; acc[7]  += a4.y * b4.w;
            acc[8]  += a4.z * b4.x; acc[9]  += a4.z * b4.y; acc[10] += a4.z * b4.z; acc[11] += a4.z * b4.w;
            acc[12] += a4.w * b4.x; acc[13] += a4.w * b4.y; acc[14] += a4.w * b4.z; acc[15] += a4.w * b4.w;
        }
        __syncthreads();
    }
#pragma unroll
    for (int i = 0; i < 4; i++)
#pragma unroll
        for (int j = 0; j < 4; j++)
            C[(size_t)(m0 + ty * 4 + i) * ldc + n0 + tx * 4 + j] =
                acc[i * 4 + j] + __ldg(&bias[n0 + tx * 4 + j]);
}

// ---------------- GRU scan: 16 blocks x 1024 threads, block-local syncs ----------------
// Stage A: 8 threads per hidden unit (128 units). Stage B: 32 warps x 1 categorical.
// prior logits hoisted to a post-scan GEMM over h_seq.
__global__ __launch_bounds__(1024) void rssm_scan_kernel(
    const float* __restrict__ wih, const float* __restrict__ whh,
    const float* __restrict__ bih, const float* __restrict__ bhh,
    const float* __restrict__ post_w, const float* __restrict__ actions,
    float* __restrict__ out) {
    int tid = threadIdx.x;
    int b = blockIdx.x;
    __shared__ __align__(16) float hb[2][128];
    __shared__ int zidx_s[32];
    __shared__ float act_s[8];
    if (tid < 128) hb[0][tid] = 0.f;

    for (int t = 0; t < TT; t++) {
        int p = t & 1;
        float* hprev = hb[p];
        float* hnext = hb[p ^ 1];
        if (tid < 6) act_s[tid] = __ldg(&actions[(b * TT + t) * 6 + tid]);
        __syncthreads();
        // ---- stage A: gates + h_new ----
        {
            int j = tid >> 3, l = tid & 7;
            const float* whh_r = whh + (size_t)j * 128;
            const float* whh_z = whh + (size_t)(j + 128) * 128;
            const float* whh_n = whh + (size_t)(j + 256) * 128;
            float ar = 0.f, az = 0.f, ani = 0.f, anh = 0.f;
#pragma unroll
            for (int i = 0; i < 16; i++) {
                int k = l + i * 8;
                float h = hprev[k];
                ar  += h * __ldg(&whh_r[k]);
                az  += h * __ldg(&whh_z[k]);
                anh += h * __ldg(&whh_n[k]);
            }
            const float* wih_r = wih + (size_t)j * 1030;
            const float* wih_z = wih + (size_t)(j + 128) * 1030;
            const float* wih_n = wih + (size_t)(j + 256) * 1030;
            if (t > 0) {
#pragma unroll
                for (int c = 0; c < 4; c++) {
                    int cc = l + c * 8;
                    int col = cc * 32 + zidx_s[cc];
                    ar  += __ldg(&wih_r[col]);
                    az  += __ldg(&wih_z[col]);
                    ani += __ldg(&wih_n[col]);
                }
            }
            if (l < 6) {
                float a = act_s[l];
                int col = 1024 + l;
                ar  += a * __ldg(&wih_r[col]);
                az  += a * __ldg(&wih_z[col]);
                ani += a * __ldg(&wih_n[col]);
            }
            for (int off = 4; off; off >>= 1) {
                ar  += __shfl_down_sync(0xffffffffu, ar, off, 8);
                az  += __shfl_down_sync(0xffffffffu, az, off, 8);
                ani += __shfl_down_sync(0xffffffffu, ani, off, 8);
                anh += __shfl_down_sync(0xffffffffu, anh, off, 8);
            }
            if (l == 0) {
                float r = 1.f / (1.f + expf(-(ar + __ldg(&bih[j]) + __ldg(&bhh[j]))));
                float u = 1.f / (1.f + expf(-(az + __ldg(&bih[j + 128]) + __ldg(&bhh[j + 128]))));
                float nn = tanhf(ani + __ldg(&bih[j + 256]) + r * (anh + __ldg(&bhh[j + 256])));
                float hn = (1.f - u) * nn + u * hprev[j];
                hnext[j] = hn;
                out[OUT_H + (size_t)(b * TT + t) * 128 + j] = hn;
            }
        }
        __syncthreads();
        // ---- stage B: post logits + argmax (one categorical per warp) ----
        {
            int c = tid >> 5, lane = tid & 31;
            int row = c * 32 + lane;
            const float4* hp4 = (const float4*)hnext;
            const float4* qw4 = (const float4*)(post_w + (size_t)row * 384);
            float aq = 0.f;
#pragma unroll
            for (int i = 0; i < 32; i++) {
                float4 h4 = hp4[i];
                float4 v4 = __ldg(qw4 + i);
                aq += h4.x * v4.x + h4.y * v4.y + h4.z * v4.z + h4.w * v4.w;
            }
            aq += d_fpart[(size_t)(b * TT + t) * 1024 + row];
            size_t n_idx = (size_t)(b * TT + t) * 1024 + row;
            out[OUT_POST + n_idx] = aq;
            float bv = aq; int bi = lane;
#pragma unroll
            for (int off = 16; off; off >>= 1) {
                float ov = __shfl_xor_sync(0xffffffffu, bv, off);
                int oi = __shfl_xor_sync(0xffffffffu, bi, off);
                if (ov > bv || (ov == bv && oi < bi)) { bv = ov; bi = oi; }
            }
            out[OUT_Z + n_idx] = (lane == bi) ? 1.f : 0.f;
            if (lane == 0) zidx_s[c] = bi;
        }
    }
}

// ---------------- host launch ----------------
extern "C" void kernel_launch(void* const* d_in, const int* in_sizes, int n_in,
                              void* d_out, int out_size) {
    const float* states  = (const float*)d_in[0];
    const float* actions = (const float*)d_in[1];
    const float* conv1_w = (const float*)d_in[2];
    const float* conv1_b = (const float*)d_in[3];
    const float* ln1_g   = (const float*)d_in[4];
    const float* ln1_b   = (const float*)d_in[5];
    const float* conv2_w = (const float*)d_in[6];
    const float* conv2_b = (const float*)d_in[7];
    const float* ln2_g   = (const float*)d_in[8];
    const float* ln2_b   = (const float*)d_in[9];
    const float* conv3_w = (const float*)d_in[10];
    const float* conv3_b = (const float*)d_in[11];
    const float* ln3_g   = (const float*)d_in[12];
    const float* ln3_b   = (const float*)d_in[13];
    const float* conv4_w = (const float*)d_in[14];
    const float* conv4_b = (const float*)d_in[15];
    const float* ln4_g   = (const float*)d_in[16];
    const float* ln4_b   = (const float*)d_in[17];
    const float* fc_w    = (const float*)d_in[18];
    const float* fc_b    = (const float*)d_in[19];
    const float* gru_wih = (const float*)d_in[20];
    const float* gru_whh = (const float*)d_in[21];
    const float* gru_bih = (const float*)d_in[22];
    const float* gru_bhh = (const float*)d_in[23];
    const float* prior_w = (const float*)d_in[24];
    const float* prior_b = (const float*)d_in[25];
    const float* post_w  = (const float*)d_in[26];
    const float* post_b  = (const float*)d_in[27];
    float* out = (float*)d_out;

    auto c2 = conv_kernel<32, 32, 64, 16, 8, 2, 36, 1>;
    auto c3 = conv_kernel<64, 16, 128, 16, 8, 8, 20, 2>;
    auto c4 = conv_kernel<128, 8, 256, 16, 4, 32, 12, 3>;
    const int sm1 = (3 * 66 * 68 + 32 * 48) * 4;
    const int sm2 = (16 * 8 * 16 + 2 * (8 * 34 * 36 + 8)) * 4;
    const int sm3 = (16 * 8 * 16 + 8 * (8 * 18 * 20 + 8)) * 4;
    const int sm4 = (16 * 8 * 16 + 32 * (8 * 10 * 12 + 8)) * 4;
    cudaFuncSetAttribute(conv1_kernel, cudaFuncAttributeMaxDynamicSharedMemorySize, sm1);
    cudaFuncSetAttribute(c2, cudaFuncAttributeMaxDynamicSharedMemorySize, sm2);
    cudaFuncSetAttribute(c3, cudaFuncAttributeMaxDynamicSharedMemorySize, sm3);
    cudaFuncSetAttribute(c4, cudaFuncAttributeMaxDynamicSharedMemorySize, sm4);

    init_kernel<<<32, 256>>>();
    conv1_kernel<<<1024, 256, sm1>>>(states, conv1_w, conv1_b);
    ln_silu_kernel<32 * 32 * 32, 0><<<1024, 256>>>(ln1_g, ln1_b);
    c2<<<dim3(512, 4), 256, sm2>>>(conv2_w, conv2_b);
    ln_silu_kernel<64 * 16 * 16, 1><<<1024, 256>>>(ln2_g, ln2_b);
    c3<<<dim3(128, 8), 256, sm3>>>(conv3_w, conv3_b);
    ln_silu_kernel<128 * 8 * 8, 2><<<1024, 256>>>(ln3_g, ln3_b);
    c4<<<dim3(32, 16), 256, sm4>>>(conv4_w, conv4_b);
    ln_silu_kernel<256 * 4 * 4, 3><<<1024, 256>>>(ln4_g, ln4_b);
    gemm_kernel<4096, 4096, 0><<<dim3(16, 4), 256>>>(fc_w, fc_b, nullptr, nullptr);           // feats
    gemm_kernel<256, 384, 1><<<dim3(16, 16), 256>>>(post_w + 128, post_b, nullptr, nullptr);  // fpart
    rssm_scan_kernel<<<16, 1024>>>(gru_wih, gru_whh, gru_bih, gru_bhh,
                                   post_w, actions, out);
    // prior hoisted out of the scan: prior = h_seq @ prior_w^T + prior_b
    gemm_kernel<128, 128, 2><<<dim3(16, 16), 256>>>(prior_w, prior_b, out + OUT_H, out + OUT_PRIOR);
}

// round 13
// speedup vs baseline: 1.0001x; 1.0001x over previous
#include <cuda_runtime.h>
#include <math.h>
#include <stdint.h>

#define BATCH 16
#define TT 64
#define NSAMP 1024

__device__ float d_y1[NSAMP * 32 * 32 * 32];
__device__ float d_y2[NSAMP * 64 * 16 * 16];
__device__ float d_y3[NSAMP * 128 * 8 * 8];
__device__ float d_y4[NSAMP * 256 * 4 * 4];
__device__ float d_feats[NSAMP * 256];
__device__ float d_fpart[NSAMP * 1024];
__device__ float d_stats[4][NSAMP][2];

#define OUT_PRIOR 0
#define OUT_POST  1048576
#define OUT_H     2097152
#define OUT_Z     2228224

__global__ void init_kernel() {
    int i = blockIdx.x * 256 + threadIdx.x;
    if (i < 4 * NSAMP * 2) ((float*)d_stats)[i] = 0.f;
}

// ---------------- conv1: 3ch 64x64 -> 32ch 32x32 (PW=68, weight-swizzled) ----------------
__global__ __launch_bounds__(256) void conv1_kernel(const float* __restrict__ x,
                                                    const float* __restrict__ w,
                                                    const float* __restrict__ bias) {
    extern __shared__ float sm[];
    float* in_s = sm;                 // 3*66*68
    float* w_s  = sm + 3 * 66 * 68;   // 32*48
    int n = blockIdx.x, tid = threadIdx.x;
    for (int i = tid; i < 3 * 66 * 68; i += 256) in_s[i] = 0.f;
    for (int i = tid; i < 32 * 48; i += 256) {
        int oc = i / 48, r = i % 48;
        int pos = oc * 48 + (r & ~15) + ((((r >> 2) ^ (oc >> 2)) & 3) << 2) + (r & 3);
        w_s[pos] = w[i];
    }
    __syncthreads();
    for (int i = tid; i < 3 * 64 * 64; i += 256) {
        int c = i >> 12, r = i & 4095, y = r >> 6, xx = r & 63;
        in_s[(c * 66 + y + 1) * 68 + xx + 1] = x[(size_t)n * 12288 + i];
    }
    __syncthreads();
    float s_sum = 0.f, s_sq = 0.f;
    int ocg = tid & 7, qb = tid >> 3;
    int swz = ocg & 3;
#pragma unroll 1
    for (int qi = 0; qi < 8; qi++) {
        int q = qb + qi * 32;
        int oy = q >> 3, ox0 = (q & 7) << 2;
        float acc[16];
#pragma unroll
        for (int i = 0; i < 16; i++) acc[i] = 0.f;
#pragma unroll
        for (int c = 0; c < 3; c++)
#pragma unroll
            for (int ky = 0; ky < 4; ky++) {
                const float4* xp = (const float4*)(in_s + (c * 66 + oy * 2 + ky) * 68 + ox0 * 2);
                float xr[12];
                *(float4*)&xr[0] = xp[0];
                *(float4*)&xr[4] = xp[1];
                *(float4*)&xr[8] = xp[2];
                int kys = (ky ^ swz) << 2;
#pragma unroll
                for (int o = 0; o < 4; o++) {
                    float4 wv = *(const float4*)(w_s + (ocg * 4 + o) * 48 + c * 16 + kys);
#pragma unroll
                    for (int m = 0; m < 4; m++)
                        acc[o * 4 + m] += wv.x * xr[2 * m] + wv.y * xr[2 * m + 1]
                                        + wv.z * xr[2 * m + 2] + wv.w * xr[2 * m + 3];
                }
            }
#pragma unroll
        for (int o = 0; o < 4; o++) {
            int oc = ocg * 4 + o;
            float bv = __ldg(&bias[oc]);
#pragma unroll
            for (int m = 0; m < 4; m++) {
                float v = acc[o * 4 + m] + bv;
                d_y1[(((size_t)n * 32 + oc) * 32 + oy) * 32 + ox0 + m] = v;
                s_sum += v; s_sq += v * v;
            }
        }
    }
    for (int off = 16; off; off >>= 1) {
        s_sum += __shfl_down_sync(0xffffffffu, s_sum, off);
        s_sq  += __shfl_down_sync(0xffffffffu, s_sq, off);
    }
    if ((tid & 31) == 0) {
        atomicAdd(&d_stats[0][n][0], s_sum);
        atomicAdd(&d_stats[0][n][1], s_sq);
    }
}

// ---------------- generic conv (stages 1..3): PX-wide register tiles ----------------
template <int STAGE> __device__ __forceinline__ const float* conv_in() {
    if constexpr (STAGE == 1) return d_y1; else if constexpr (STAGE == 2) return d_y2; else return d_y3;
}
template <int STAGE> __device__ __forceinline__ float* conv_out() {
    if constexpr (STAGE == 1) return d_y2; else if constexpr (STAGE == 2) return d_y3; else return d_y4;
}

template <int CIN, int H, int COUT, int OCB, int PX, int NS, int PW, int STAGE>
__global__ __launch_bounds__(256) void conv_kernel(const float* __restrict__ w,
                                                   const float* __restrict__ bias) {
    constexpr int W = H, OH = H / 2, OW = H / 2, PH = H + 2;
    constexpr int TO = 32 / PX;
    constexpr int OCG = OCB / TO;
    constexpr int QN = OH * OW / PX;
    constexpr int CHSTRIDE = 8 * PH * PW + 8;
    constexpr int WCH = OCB * 8 * 16;
    constexpr int NROWS = NS * 8 * PH;
    extern __shared__ float sm[];
    float* w_s = sm;
    float* in_s = sm + WCH;
    const float* xin = conv_in<STAGE>();
    float* yout = conv_out<STAGE>();
    int tid = threadIdx.x;
    int n0 = blockIdx.x * NS;
    int oc0 = blockIdx.y * OCB;

    int smp = tid / (OCG * QN);
    int rem = tid % (OCG * QN);
    int ocg = rem % OCG;
    int qn = rem / OCG;
    int oy = qn / (OW / PX);
    int ox0 = (qn % (OW / PX)) * PX;
    int n = n0 + smp;

    float acc[32];
#pragma unroll
    for (int i = 0; i < 32; i++) acc[i] = 0.f;

    for (int icb = 0; icb < CIN / 8; icb++) {
        __syncthreads();
        for (int i = tid; i < WCH; i += 256) {
            int r = i & 127;
            int pos = (i & ~15) | ((((i >> 2) ^ (i >> 9)) & 3) << 2) | (i & 3);
            w_s[pos] = w[(size_t)(oc0 + (i >> 7)) * CIN * 16 + icb * 128 + r];
        }
        for (int r = tid; r < NROWS; r += 256) {
            int s = r / (8 * PH);
            int rem2 = r - s * (8 * PH);
            int c = rem2 / PH;
            int y = rem2 - c * PH;
            float* base = in_s + s * CHSTRIDE + (c * PH + y) * PW;
            if (y == 0 || y == PH - 1) {
#pragma unroll
                for (int j = 0; j < PW; j++) base[j] = 0.f;
            } else {
                base[0] = 0.f;
#pragma unroll
                for (int j = W + 1; j < PW; j++) base[j] = 0.f;
                const float4* src = (const float4*)(xin +
                    (((size_t)(n0 + s) * CIN + icb * 8 + c) * H + (y - 1)) * W);
#pragma unroll
                for (int j = 0; j < W / 4; j++) {
                    float4 v = __ldg(src + j);
                    base[1 + 4 * j] = v.x; base[2 + 4 * j] = v.y;
                    base[3 + 4 * j] = v.z; base[4 + 4 * j] = v.w;
                }
            }
        }
        __syncthreads();
#pragma unroll
        for (int icl = 0; icl < 8; icl++) {
            const float* inc = in_s + smp * CHSTRIDE + icl * PH * PW;
            const float* wb = w_s + icl * 16;
#pragma unroll
            for (int ky = 0; ky < 4; ky++) {
                const float4* xp = (const float4*)(inc + (oy * 2 + ky) * PW + ox0 * 2);
                float xr[2 * PX + 4];
#pragma unroll
                for (int f = 0; f < PX / 2 + 1; f++) *(float4*)&xr[4 * f] = xp[f];
#pragma unroll
                for (int o = 0; o < TO; o++) {
                    int ol = ocg * TO + o;
                    float4 wv = *(const float4*)(wb + ol * 128 + ((ky ^ ((ol >> 2) & 3)) << 2));
#pragma unroll
                    for (int m = 0; m < PX; m++)
                        acc[o * PX + m] += wv.x * xr[2 * m] + wv.y * xr[2 * m + 1]
                                         + wv.z * xr[2 * m + 2] + wv.w * xr[2 * m + 3];
                }
            }
        }
    }
    float s_sum = 0.f, s_sq = 0.f;
#pragma unroll
    for (int o = 0; o < TO; o++) {
        int oc = oc0 + ocg * TO + o;
        float bv = __ldg(&bias[oc]);
#pragma unroll
        for (int m = 0; m < PX; m++) {
            float v = acc[o * PX + m] + bv;
            yout[(((size_t)n * COUT + oc) * OH + oy) * OW + ox0 + m] = v;
            s_sum += v; s_sq += v * v;
        }
    }
    constexpr int RW = (OCG * QN >= 32) ? 32 : (OCG * QN);
    for (int off = RW / 2; off; off >>= 1) {
        s_sum += __shfl_down_sync(0xffffffffu, s_sum, off, RW);
        s_sq  += __shfl_down_sync(0xffffffffu, s_sq, off, RW);
    }
    if ((tid % RW) == 0) {
        atomicAdd(&d_stats[STAGE][n][0], s_sum);
        atomicAdd(&d_stats[STAGE][n][1], s_sq);
    }
}

// ---------------- LayerNorm + SiLU (vectorized) ----------------
template <int CHW, int STAGE>
__global__ void ln_silu_kernel(const float* __restrict__ g, const float* __restrict__ bp) {
    float* y;
    if constexpr (STAGE == 0) y = d_y1;
    else if constexpr (STAGE == 1) y = d_y2;
    else if constexpr (STAGE == 2) y = d_y3;
    else y = d_y4;
    int n = blockIdx.x;
    float mean = d_stats[STAGE][n][0] * (1.f / CHW);
    float var = d_stats[STAGE][n][1] * (1.f / CHW) - mean * mean;
    float inv = rsqrtf(var + 1e-5f);
    float4* yp = (float4*)(y + (size_t)n * CHW);
    const float4* gp = (const float4*)g;
    const float4* bpp = (const float4*)bp;
    for (int i = threadIdx.x; i < CHW / 4; i += blockDim.x) {
        float4 v4 = yp[i], g4 = __ldg(gp + i), b4 = __ldg(bpp + i);
        float a0 = (v4.x - mean) * inv * g4.x + b4.x;
        float a1 = (v4.y - mean) * inv * g4.y + b4.y;
        float a2 = (v4.z - mean) * inv * g4.z + b4.z;
        float a3 = (v4.w - mean) * inv * g4.w + b4.w;
        v4.x = a0 / (1.f + __expf(-a0));
        v4.y = a1 / (1.f + __expf(-a1));
        v4.z = a2 / (1.f + __expf(-a2));
        v4.w = a3 / (1.f + __expf(-a3));
        yp[i] = v4;
    }
}

// ---------------- SGEMM: C[M,N] = A[M,K] * B[N,:K]^T + bias ----------------
// WHICH=0: A=d_y4 -> C=d_feats. WHICH=1: A=d_feats -> C=d_fpart. WHICH=2: ext ptrs.
// __device__ globals MUST be resolved in device code (host-side symbol refs
// give the host shadow address — silently "works" via ATS on GB300).
template <int KK, int LDB, int WHICH>
__global__ __launch_bounds__(256) void gemm_kernel(const float* __restrict__ Bmat,
                                                   const float* __restrict__ bias,
                                                   const float* __restrict__ Aext,
                                                   float* __restrict__ Cext) {
    const float* A = (WHICH == 0) ? d_y4 : (WHICH == 1) ? d_feats : Aext;
    float* C = (WHICH == 0) ? d_feats : (WHICH == 1) ? d_fpart : Cext;
    const int ldc = gridDim.y * 64;
    __shared__ float As[16][68];
    __shared__ float Bs[16][68];
    int m0 = blockIdx.x * 64, n0 = blockIdx.y * 64;
    int tid = threadIdx.x;
    int tx = tid % 16, ty = tid / 16;
    float acc[16];
#pragma unroll
    for (int i = 0; i < 16; i++) acc[i] = 0.f;
    for (int k0 = 0; k0 < KK; k0 += 16) {
#pragma unroll
        for (int e = 0; e < 4; e++) {
            int f = tid + e * 256;
            int m = f >> 4, k = f & 15;
            As[k][m] = A[(size_t)(m0 + m) * KK + k0 + k];
            Bs[k][m] = Bmat[(size_t)(n0 + m) * LDB + k0 + k];
        }
        __syncthreads();
#pragma unroll
        for (int k = 0; k < 16; k++) {
            float4 a4 = *(const float4*)&As[k][ty * 4];
            float4 b4 = *(const float4*)&Bs[k][tx * 4];
            acc[0]  += a4.x * b4.x; acc[1]  += a4.x * b4.y; acc[2]  += a4.x * b4.z; acc[3]  += a4.x * b4.w;
            acc[4]  += a4.y * b4.x; acc[5]  += a4.y * b4.y; acc[6]  += a4.y * b4.z; acc[7]  += a4.y * b4.w;
            acc[8]  += a4.z * b4.x; acc[9]  += a4.z * b4.y; acc[10] += a4.z * b4.z; acc[11] += a4.z * b4.w;
            acc[12] += a4.w * b4.x; acc[13] += a4.w * b4.y; acc[14] += a4.w * b4.z; acc[15] += a4.w * b4.w;
        }
        __syncthreads();
    }
#pragma unroll
    for (int i = 0; i < 4; i++)
#pragma unroll
        for (int j = 0; j < 4; j++)
            C[(size_t)(m0 + ty * 4 + i) * ldc + n0 + tx * 4 + j] =
                acc[i * 4 + j] + __ldg(&bias[n0 + tx * 4 + j]);
}

// ---------------- GRU scan: 16 blocks x 1024 threads, block-local syncs ----------------
// Stage A: 8 threads per hidden unit (128 units). Stage B: 32 warps x 1 categorical.
// prior logits hoisted to a post-scan GEMM over h_seq.
__global__ __launch_bounds__(1024) void rssm_scan_kernel(
    const float* __restrict__ wih, const float* __restrict__ whh,
    const float* __restrict__ bih, const float* __restrict__ bhh,
    const float* __restrict__ post_w, const float* __restrict__ actions,
    float* __restrict__ out) {
    int tid = threadIdx.x;
    int b = blockIdx.x;
    __shared__ __align__(16) float hb[2][128];
    __shared__ int zidx_s[32];
    __shared__ float act_s[8];
    if (tid < 128) hb[0][tid] = 0.f;

    for (int t = 0; t < TT; t++) {
        int p = t & 1;
        float* hprev = hb[p];
        float* hnext = hb[p ^ 1];
        if (tid < 6) act_s[tid] = __ldg(&actions[(b * TT + t) * 6 + tid]);
        __syncthreads();
        // ---- stage A: gates + h_new ----
        {
            int j = tid >> 3, l = tid & 7;
            const float* whh_r = whh + (size_t)j * 128;
            const float* whh_z = whh + (size_t)(j + 128) * 128;
            const float* whh_n = whh + (size_t)(j + 256) * 128;
            float ar = 0.f, az = 0.f, ani = 0.f, anh = 0.f;
#pragma unroll
            for (int i = 0; i < 16; i++) {
                int k = l + i * 8;
                float h = hprev[k];
                ar  += h * __ldg(&whh_r[k]);
                az  += h * __ldg(&whh_z[k]);
                anh += h * __ldg(&whh_n[k]);
            }
            const float* wih_r = wih + (size_t)j * 1030;
            const float* wih_z = wih + (size_t)(j + 128) * 1030;
            const float* wih_n = wih + (size_t)(j + 256) * 1030;
            if (t > 0) {
#pragma unroll
                for (int c = 0; c < 4; c++) {
                    int cc = l + c * 8;
                    int col = cc * 32 + zidx_s[cc];
                    ar  += __ldg(&wih_r[col]);
                    az  += __ldg(&wih_z[col]);
                    ani += __ldg(&wih_n[col]);
                }
            }
            if (l < 6) {
                float a = act_s[l];
                int col = 1024 + l;
                ar  += a * __ldg(&wih_r[col]);
                az  += a * __ldg(&wih_z[col]);
                ani += a * __ldg(&wih_n[col]);
            }
            for (int off = 4; off; off >>= 1) {
                ar  += __shfl_down_sync(0xffffffffu, ar, off, 8);
                az  += __shfl_down_sync(0xffffffffu, az, off, 8);
                ani += __shfl_down_sync(0xffffffffu, ani, off, 8);
                anh += __shfl_down_sync(0xffffffffu, anh, off, 8);
            }
            if (l == 0) {
                float r = 1.f / (1.f + expf(-(ar + __ldg(&bih[j]) + __ldg(&bhh[j]))));
                float u = 1.f / (1.f + expf(-(az + __ldg(&bih[j + 128]) + __ldg(&bhh[j + 128]))));
                float nn = tanhf(ani + __ldg(&bih[j + 256]) + r * (anh + __ldg(&bhh[j + 256])));
                float hn = (1.f - u) * nn + u * hprev[j];
                hnext[j] = hn;
                out[OUT_H + (size_t)(b * TT + t) * 128 + j] = hn;
            }
        }
        __syncthreads();
        // ---- stage B: post logits + argmax (one categorical per warp) ----
        {
            int c = tid >> 5, lane = tid & 31;
            int row = c * 32 + lane;
            const float4* hp4 = (const float4*)hnext;
            const float4* qw4 = (const float4*)(post_w + (size_t)row * 384);
            float aq = 0.f;
#pragma unroll
            for (int i = 0; i < 32; i++) {
                float4 h4 = hp4[i];
                float4 v4 = __ldg(qw4 + i);
                aq += h4.x * v4.x + h4.y * v4.y + h4.z * v4.z + h4.w * v4.w;
            }
            aq += d_fpart[(size_t)(b * TT + t) * 1024 + row];
            size_t n_idx = (size_t)(b * TT + t) * 1024 + row;
            out[OUT_POST + n_idx] = aq;
            float bv = aq; int bi = lane;
#pragma unroll
            for (int off = 16; off; off >>= 1) {
                float ov = __shfl_xor_sync(0xffffffffu, bv, off);
                int oi = __shfl_xor_sync(0xffffffffu, bi, off);
                if (ov > bv || (ov == bv && oi < bi)) { bv = ov; bi = oi; }
            }
            out[OUT_Z + n_idx] = (lane == bi) ? 1.f : 0.f;
            if (lane == 0) zidx_s[c] = bi;
        }
    }
}

// ---------------- host launch ----------------
extern "C" void kernel_launch(void* const* d_in, const int* in_sizes, int n_in,
                              void* d_out, int out_size) {
    const float* states  = (const float*)d_in[0];
    const float* actions = (const float*)d_in[1];
    const float* conv1_w = (const float*)d_in[2];
    const float* conv1_b = (const float*)d_in[3];
    const float* ln1_g   = (const float*)d_in[4];
    const float* ln1_b   = (const float*)d_in[5];
    const float* conv2_w = (const float*)d_in[6];
    const float* conv2_b = (const float*)d_in[7];
    const float* ln2_g   = (const float*)d_in[8];
    const float* ln2_b   = (const float*)d_in[9];
    const float* conv3_w = (const float*)d_in[10];
    const float* conv3_b = (const float*)d_in[11];
    const float* ln3_g   = (const float*)d_in[12];
    const float* ln3_b   = (const float*)d_in[13];
    const float* conv4_w = (const float*)d_in[14];
    const float* conv4_b = (const float*)d_in[15];
    const float* ln4_g   = (const float*)d_in[16];
    const float* ln4_b   = (const float*)d_in[17];
    const float* fc_w    = (const float*)d_in[18];
    const float* fc_b    = (const float*)d_in[19];
    const float* gru_wih = (const float*)d_in[20];
    const float* gru_whh = (const float*)d_in[21];
    const float* gru_bih = (const float*)d_in[22];
    const float* gru_bhh = (const float*)d_in[23];
    const float* prior_w = (const float*)d_in[24];
    const float* prior_b = (const float*)d_in[25];
    const float* post_w  = (const float*)d_in[26];
    const float* post_b  = (const float*)d_in[27];
    float* out = (float*)d_out;

    auto c2 = conv_kernel<32, 32, 64, 16, 8, 2, 36, 1>;
    auto c3 = conv_kernel<64, 16, 128, 16, 8, 8, 20, 2>;
    auto c4 = conv_kernel<128, 8, 256, 16, 4, 32, 12, 3>;
    const int sm1 = (3 * 66 * 68 + 32 * 48) * 4;
    const int sm2 = (16 * 8 * 16 + 2 * (8 * 34 * 36 + 8)) * 4;
    const int sm3 = (16 * 8 * 16 + 8 * (8 * 18 * 20 + 8)) * 4;
    const int sm4 = (16 * 8 * 16 + 32 * (8 * 10 * 12 + 8)) * 4;
    cudaFuncSetAttribute(conv1_kernel, cudaFuncAttributeMaxDynamicSharedMemorySize, sm1);
    cudaFuncSetAttribute(c2, cudaFuncAttributeMaxDynamicSharedMemorySize, sm2);
    cudaFuncSetAttribute(c3, cudaFuncAttributeMaxDynamicSharedMemorySize, sm3);
    cudaFuncSetAttribute(c4, cudaFuncAttributeMaxDynamicSharedMemorySize, sm4);

    init_kernel<<<32, 256>>>();
    conv1_kernel<<<1024, 256, sm1>>>(states, conv1_w, conv1_b);
    ln_silu_kernel<32 * 32 * 32, 0><<<1024, 256>>>(ln1_g, ln1_b);
    c2<<<dim3(512, 4), 256, sm2>>>(conv2_w, conv2_b);
    ln_silu_kernel<64 * 16 * 16, 1><<<1024, 256>>>(ln2_g, ln2_b);
    c3<<<dim3(128, 8), 256, sm3>>>(conv3_w, conv3_b);
    ln_silu_kernel<128 * 8 * 8, 2><<<1024, 256>>>(ln3_g, ln3_b);
    c4<<<dim3(32, 16), 256, sm4>>>(conv4_w, conv4_b);
    ln_silu_kernel<256 * 4 * 4, 3><<<1024, 256>>>(ln4_g, ln4_b);
    gemm_kernel<4096, 4096, 0><<<dim3(16, 4), 256>>>(fc_w, fc_b, nullptr, nullptr);           // feats
    gemm_kernel<256, 384, 1><<<dim3(16, 16), 256>>>(post_w + 128, post_b, nullptr, nullptr);  // fpart
    rssm_scan_kernel<<<16, 1024>>>(gru_wih, gru_whh, gru_bih, gru_bhh,
                                   post_w, actions, out);
    // prior hoisted out of the scan: prior = h_seq @ prior_w^T + prior_b
    gemm_kernel<128, 128, 2><<<dim3(16, 16), 256>>>(prior_w, prior_b, out + OUT_H, out + OUT_PRIOR);
}

// round 14
// speedup vs baseline: 1.0005x; 1.0004x over previous
#include <cuda_runtime.h>
#include <math.h>
#include <stdint.h>

#define BATCH 16
#define TT 64
#define NSAMP 1024

__device__ float d_y1[NSAMP * 32 * 32 * 32];
__device__ float d_y2[NSAMP * 64 * 16 * 16];
__device__ float d_y3[NSAMP * 128 * 8 * 8];
__device__ float d_y4[NSAMP * 256 * 4 * 4];
__device__ float d_feats[NSAMP * 256];
__device__ float d_fpart[NSAMP * 1024];
__device__ float d_stats[4][NSAMP][2];
__device__ float d_pwt[128 * 1024];   // post_w h-part, transposed k-major

#define OUT_PRIOR 0
#define OUT_POST  1048576
#define OUT_H     2097152
#define OUT_Z     2228224

__global__ void init_kernel() {
    int i = blockIdx.x * 256 + threadIdx.x;
    if (i < 4 * NSAMP * 2) ((float*)d_stats)[i] = 0.f;
}

// transpose post_w[:, 0:128] (row-major 1024x384) -> d_pwt[128][1024]
__global__ void pwt_transpose(const float* __restrict__ post_w) {
    int idx = blockIdx.x * 256 + threadIdx.x;
    if (idx >= 128 * 1024) return;
    int i = idx >> 10, row = idx & 1023;
    d_pwt[idx] = post_w[(size_t)row * 384 + i];
}

// ---------------- conv1: 3ch 64x64 -> 32ch 32x32 (PW=68, weight-swizzled) ----------------
__global__ __launch_bounds__(256) void conv1_kernel(const float* __restrict__ x,
                                                    const float* __restrict__ w,
                                                    const float* __restrict__ bias) {
    extern __shared__ float sm[];
    float* in_s = sm;                 // 3*66*68
    float* w_s  = sm + 3 * 66 * 68;   // 32*48
    int n = blockIdx.x, tid = threadIdx.x;
    for (int i = tid; i < 3 * 66 * 68; i += 256) in_s[i] = 0.f;
    for (int i = tid; i < 32 * 48; i += 256) {
        int oc = i / 48, r = i % 48;
        int pos = oc * 48 + (r & ~15) + ((((r >> 2) ^ (oc >> 2)) & 3) << 2) + (r & 3);
        w_s[pos] = w[i];
    }
    __syncthreads();
    for (int i = tid; i < 3 * 64 * 64; i += 256) {
        int c = i >> 12, r = i & 4095, y = r >> 6, xx = r & 63;
        in_s[(c * 66 + y + 1) * 68 + xx + 1] = x[(size_t)n * 12288 + i];
    }
    __syncthreads();
    float s_sum = 0.f, s_sq = 0.f;
    int ocg = tid & 7, qb = tid >> 3;
    int swz = ocg & 3;
#pragma unroll 1
    for (int qi = 0; qi < 8; qi++) {
        int q = qb + qi * 32;
        int oy = q >> 3, ox0 = (q & 7) << 2;
        float acc[16];
#pragma unroll
        for (int i = 0; i < 16; i++) acc[i] = 0.f;
#pragma unroll
        for (int c = 0; c < 3; c++)
#pragma unroll
            for (int ky = 0; ky < 4; ky++) {
                const float4* xp = (const float4*)(in_s + (c * 66 + oy * 2 + ky) * 68 + ox0 * 2);
                float xr[12];
                *(float4*)&xr[0] = xp[0];
                *(float4*)&xr[4] = xp[1];
                *(float4*)&xr[8] = xp[2];
                int kys = (ky ^ swz) << 2;
#pragma unroll
                for (int o = 0; o < 4; o++) {
                    float4 wv = *(const float4*)(w_s + (ocg * 4 + o) * 48 + c * 16 + kys);
#pragma unroll
                    for (int m = 0; m < 4; m++)
                        acc[o * 4 + m] += wv.x * xr[2 * m] + wv.y * xr[2 * m + 1]
                                        + wv.z * xr[2 * m + 2] + wv.w * xr[2 * m + 3];
                }
            }
#pragma unroll
        for (int o = 0; o < 4; o++) {
            int oc = ocg * 4 + o;
            float bv = __ldg(&bias[oc]);
#pragma unroll
            for (int m = 0; m < 4; m++) {
                float v = acc[o * 4 + m] + bv;
                d_y1[(((size_t)n * 32 + oc) * 32 + oy) * 32 + ox0 + m] = v;
                s_sum += v; s_sq += v * v;
            }
        }
    }
    for (int off = 16; off; off >>= 1) {
        s_sum += __shfl_down_sync(0xffffffffu, s_sum, off);
        s_sq  += __shfl_down_sync(0xffffffffu, s_sq, off);
    }
    if ((tid & 31) == 0) {
        atomicAdd(&d_stats[0][n][0], s_sum);
        atomicAdd(&d_stats[0][n][1], s_sq);
    }
}

// ---------------- generic conv (stages 1..3): PX-wide register tiles ----------------
template <int STAGE> __device__ __forceinline__ const float* conv_in() {
    if constexpr (STAGE == 1) return d_y1; else if constexpr (STAGE == 2) return d_y2; else return d_y3;
}
template <int STAGE> __device__ __forceinline__ float* conv_out() {
    if constexpr (STAGE == 1) return d_y2; else if constexpr (STAGE == 2) return d_y3; else return d_y4;
}

template <int CIN, int H, int COUT, int OCB, int PX, int NS, int PW, int STAGE>
__global__ __launch_bounds__(256) void conv_kernel(const float* __restrict__ w,
                                                   const float* __restrict__ bias) {
    constexpr int W = H, OH = H / 2, OW = H / 2, PH = H + 2;
    constexpr int TO = 32 / PX;
    constexpr int OCG = OCB / TO;
    constexpr int QN = OH * OW / PX;
    constexpr int CHSTRIDE = 8 * PH * PW + 8;
    constexpr int WCH = OCB * 8 * 16;
    constexpr int NROWS = NS * 8 * PH;
    extern __shared__ float sm[];
    float* w_s = sm;
    float* in_s = sm + WCH;
    const float* xin = conv_in<STAGE>();
    float* yout = conv_out<STAGE>();
    int tid = threadIdx.x;
    int n0 = blockIdx.x * NS;
    int oc0 = blockIdx.y * OCB;

    int smp = tid / (OCG * QN);
    int rem = tid % (OCG * QN);
    int ocg = rem % OCG;
    int qn = rem / OCG;
    int oy = qn / (OW / PX);
    int ox0 = (qn % (OW / PX)) * PX;
    int n = n0 + smp;

    float acc[32];
#pragma unroll
    for (int i = 0; i < 32; i++) acc[i] = 0.f;

    for (int icb = 0; icb < CIN / 8; icb++) {
        __syncthreads();
        for (int i = tid; i < WCH; i += 256) {
            int r = i & 127;
            int pos = (i & ~15) | ((((i >> 2) ^ (i >> 9)) & 3) << 2) | (i & 3);
            w_s[pos] = w[(size_t)(oc0 + (i >> 7)) * CIN * 16 + icb * 128 + r];
        }
        for (int r = tid; r < NROWS; r += 256) {
            int s = r / (8 * PH);
            int rem2 = r - s * (8 * PH);
            int c = rem2 / PH;
            int y = rem2 - c * PH;
            float* base = in_s + s * CHSTRIDE + (c * PH + y) * PW;
            if (y == 0 || y == PH - 1) {
#pragma unroll
                for (int j = 0; j < PW; j++) base[j] = 0.f;
            } else {
                base[0] = 0.f;
#pragma unroll
                for (int j = W + 1; j < PW; j++) base[j] = 0.f;
                const float4* src = (const float4*)(xin +
                    (((size_t)(n0 + s) * CIN + icb * 8 + c) * H + (y - 1)) * W);
#pragma unroll
                for (int j = 0; j < W / 4; j++) {
                    float4 v = __ldg(src + j);
                    base[1 + 4 * j] = v.x; base[2 + 4 * j] = v.y;
                    base[3 + 4 * j] = v.z; base[4 + 4 * j] = v.w;
                }
            }
        }
        __syncthreads();
#pragma unroll
        for (int icl = 0; icl < 8; icl++) {
            const float* inc = in_s + smp * CHSTRIDE + icl * PH * PW;
            const float* wb = w_s + icl * 16;
#pragma unroll
            for (int ky = 0; ky < 4; ky++) {
                const float4* xp = (const float4*)(inc + (oy * 2 + ky) * PW + ox0 * 2);
                float xr[2 * PX + 4];
#pragma unroll
                for (int f = 0; f < PX / 2 + 1; f++) *(float4*)&xr[4 * f] = xp[f];
#pragma unroll
                for (int o = 0; o < TO; o++) {
                    int ol = ocg * TO + o;
                    float4 wv = *(const float4*)(wb + ol * 128 + ((ky ^ ((ol >> 2) & 3)) << 2));
#pragma unroll
                    for (int m = 0; m < PX; m++)
                        acc[o * PX + m] += wv.x * xr[2 * m] + wv.y * xr[2 * m + 1]
                                         + wv.z * xr[2 * m + 2] + wv.w * xr[2 * m + 3];
                }
            }
        }
    }
    float s_sum = 0.f, s_sq = 0.f;
#pragma unroll
    for (int o = 0; o < TO; o++) {
        int oc = oc0 + ocg * TO + o;
        float bv = __ldg(&bias[oc]);
#pragma unroll
        for (int m = 0; m < PX; m++) {
            float v = acc[o * PX + m] + bv;
            yout[(((size_t)n * COUT + oc) * OH + oy) * OW + ox0 + m] = v;
            s_sum += v; s_sq += v * v;
        }
    }
    constexpr int RW = (OCG * QN >= 32) ? 32 : (OCG * QN);
    for (int off = RW / 2; off; off >>= 1) {
        s_sum += __shfl_down_sync(0xffffffffu, s_sum, off, RW);
        s_sq  += __shfl_down_sync(0xffffffffu, s_sq, off, RW);
    }
    if ((tid % RW) == 0) {
        atomicAdd(&d_stats[STAGE][n][0], s_sum);
        atomicAdd(&d_stats[STAGE][n][1], s_sq);
    }
}

// ---------------- LayerNorm + SiLU (vectorized) ----------------
template <int CHW, int STAGE>
__global__ void ln_silu_kernel(const float* __restrict__ g, const float* __restrict__ bp) {
    float* y;
    if constexpr (STAGE == 0) y = d_y1;
    else if constexpr (STAGE == 1) y = d_y2;
    else if constexpr (STAGE == 2) y = d_y3;
    else y = d_y4;
    int n = blockIdx.x;
    float mean = d_stats[STAGE][n][0] * (1.f / CHW);
    float var = d_stats[STAGE][n][1] * (1.f / CHW) - mean * mean;
    float inv = rsqrtf(var + 1e-5f);
    float4* yp = (float4*)(y + (size_t)n * CHW);
    const float4* gp = (const float4*)g;
    const float4* bpp = (const float4*)bp;
    for (int i = threadIdx.x; i < CHW / 4; i += blockDim.x) {
        float4 v4 = yp[i], g4 = __ldg(gp + i), b4 = __ldg(bpp + i);
        float a0 = (v4.x - mean) * inv * g4.x + b4.x;
        float a1 = (v4.y - mean) * inv * g4.y + b4.y;
        float a2 = (v4.z - mean) * inv * g4.z + b4.z;
        float a3 = (v4.w - mean) * inv * g4.w + b4.w;
        v4.x = a0 / (1.f + __expf(-a0));
        v4.y = a1 / (1.f + __expf(-a1));
        v4.z = a2 / (1.f + __expf(-a2));
        v4.w = a3 / (1.f + __expf(-a3));
        yp[i] = v4;
    }
}

// ---------------- SGEMM: C[M,N] = A[M,K] * B[N,:K]^T + bias ----------------
// WHICH=0: A=d_y4 -> C=d_feats. WHICH=1: A=d_feats -> C=d_fpart. WHICH=2: ext ptrs.
template <int KK, int LDB, int WHICH>
__global__ __launch_bounds__(256) void gemm_kernel(const float* __restrict__ Bmat,
                                                   const float* __restrict__ bias,
                                                   const float* __restrict__ Aext,
                                                   float* __restrict__ Cext) {
    const float* A = (WHICH == 0) ? d_y4 : (WHICH == 1) ? d_feats : Aext;
    float* C = (WHICH == 0) ? d_feats : (WHICH == 1) ? d_fpart : Cext;
    const int ldc = gridDim.y * 64;
    __shared__ float As[16][68];
    __shared__ float Bs[16][68];
    int m0 = blockIdx.x * 64, n0 = blockIdx.y * 64;
    int tid = threadIdx.x;
    int tx = tid % 16, ty = tid / 16;
    float acc[16];
#pragma unroll
    for (int i = 0; i < 16; i++) acc[i] = 0.f;
    for (int k0 = 0; k0 < KK; k0 += 16) {
#pragma unroll
        for (int e = 0; e < 4; e++) {
            int f = tid + e * 256;
            int m = f >> 4, k = f & 15;
            As[k][m] = A[(size_t)(m0 + m) * KK + k0 + k];
            Bs[k][m] = Bmat[(size_t)(n0 + m) * LDB + k0 + k];
        }
        __syncthreads();
#pragma unroll
        for (int k = 0; k < 16; k++) {
            float4 a4 = *(const float4*)&As[k][ty * 4];
            float4 b4 = *(const float4*)&Bs[k][tx * 4];
            acc[0]  += a4.x * b4.x; acc[1]  += a4.x * b4.y; acc[2]  += a4.x * b4.z; acc[3]  += a4.x * b4.w;
            acc[4]  += a4.y * b4.x; acc[5]  += a4.y * b4.y; acc[6]  += a4.y * b4.z; acc[7]  += a4.y * b4.w;
            acc[8]  += a4.z * b4.x; acc[9]  += a4.z * b4.y; acc[10] += a4.z * b4.z; acc[11] += a4.z * b4.w;
            acc[12] += a4.w * b4.x; acc[13] += a4.w * b4.y; acc[14] += a4.w * b4.z; acc[15] += a4.w * b4.w;
        }
        __syncthreads();
    }
#pragma unroll
    for (int i = 0; i < 4; i++)
#pragma unroll
        for (int j = 0; j < 4; j++)
            C[(size_t)(m0 + ty * 4 + i) * ldc + n0 + tx * 4 + j] =
                acc[i * 4 + j] + __ldg(&bias[n0 + tx * 4 + j]);
}

// ---------------- GRU scan: 16 blocks x 1024 threads, coalesced loads ----------------
// whh cached in SMEM (pitch 136 -> conflict-free); stage B via transposed d_pwt.
__global__ __launch_bounds__(1024) void rssm_scan_kernel(
    const float* __restrict__ wih, const float* __restrict__ whh,
    const float* __restrict__ bih, const float* __restrict__ bhh,
    const float* __restrict__ actions, float* __restrict__ out) {
    extern __shared__ float whh_s[];   // 384 rows x 136 pitch
    __shared__ __align__(16) float hb[2][128];
    __shared__ int zidx_s[32];
    __shared__ float act_s[8];
    int tid = threadIdx.x;
    int b = blockIdx.x;
    // stage whh into SMEM once (coalesced read)
    for (int i = tid; i < 384 * 128; i += 1024) {
        int row = i >> 7, col = i & 127;
        whh_s[row * 136 + col] = __ldg(&whh[i]);
    }
    if (tid < 128) hb[0][tid] = 0.f;

    for (int t = 0; t < TT; t++) {
        int p = t & 1;
        float* hprev = hb[p];
        float* hnext = hb[p ^ 1];
        if (tid < 6) act_s[tid] = __ldg(&actions[(b * TT + t) * 6 + tid]);
        __syncthreads();
        // ---- stage A: gates + h_new (8 threads per hidden unit) ----
        {
            int j = tid >> 3, l = tid & 7;
            const float* wr = whh_s + (size_t)j * 136;
            const float* wz = whh_s + (size_t)(j + 128) * 136;
            const float* wn = whh_s + (size_t)(j + 256) * 136;
            float ar = 0.f, az = 0.f, ani = 0.f, anh = 0.f;
#pragma unroll
            for (int i = 0; i < 16; i++) {
                int k = l + i * 8;
                float h = hprev[k];
                ar  += h * wr[k];
                az  += h * wz[k];
                anh += h * wn[k];
            }
            const float* wih_r = wih + (size_t)j * 1030;
            const float* wih_z = wih + (size_t)(j + 128) * 1030;
            const float* wih_n = wih + (size_t)(j + 256) * 1030;
            if (t > 0) {
#pragma unroll
                for (int c = 0; c < 4; c++) {
                    int cc = l + c * 8;
                    int col = cc * 32 + zidx_s[cc];
                    ar  += __ldg(&wih_r[col]);
                    az  += __ldg(&wih_z[col]);
                    ani += __ldg(&wih_n[col]);
                }
            }
            if (l < 6) {
                float a = act_s[l];
                int col = 1024 + l;
                ar  += a * __ldg(&wih_r[col]);
                az  += a * __ldg(&wih_z[col]);
                ani += a * __ldg(&wih_n[col]);
            }
            for (int off = 4; off; off >>= 1) {
                ar  += __shfl_down_sync(0xffffffffu, ar, off, 8);
                az  += __shfl_down_sync(0xffffffffu, az, off, 8);
                ani += __shfl_down_sync(0xffffffffu, ani, off, 8);
                anh += __shfl_down_sync(0xffffffffu, anh, off, 8);
            }
            if (l == 0) {
                float r = 1.f / (1.f + expf(-(ar + __ldg(&bih[j]) + __ldg(&bhh[j]))));
                float u = 1.f / (1.f + expf(-(az + __ldg(&bih[j + 128]) + __ldg(&bhh[j + 128]))));
                float nn = tanhf(ani + __ldg(&bih[j + 256]) + r * (anh + __ldg(&bhh[j + 256])));
                float hn = (1.f - u) * nn + u * hprev[j];
                hnext[j] = hn;
                out[OUT_H + (size_t)(b * TT + t) * 128 + j] = hn;
            }
        }
        __syncthreads();
        // ---- stage B: post logits + argmax (one categorical per warp, coalesced) ----
        {
            int c = tid >> 5, lane = tid & 31;
            int row = c * 32 + lane;
            float aq = __ldg(&d_fpart[(size_t)(b * TT + t) * 1024 + row]);
            const float* wt = d_pwt + row;
#pragma unroll 16
            for (int i = 0; i < 128; i++)
                aq += hnext[i] * __ldg(&wt[i << 10]);
            size_t n_idx = (size_t)(b * TT + t) * 1024 + row;
            out[OUT_POST + n_idx] = aq;
            float bv = aq; int bi = lane;
#pragma unroll
            for (int off = 16; off; off >>= 1) {
                float ov = __shfl_xor_sync(0xffffffffu, bv, off);
                int oi = __shfl_xor_sync(0xffffffffu, bi, off);
                if (ov > bv || (ov == bv && oi < bi)) { bv = ov; bi = oi; }
            }
            out[OUT_Z + n_idx] = (lane == bi) ? 1.f : 0.f;
            if (lane == 0) zidx_s[c] = bi;
        }
    }
}

// ---------------- host launch ----------------
extern "C" void kernel_launch(void* const* d_in, const int* in_sizes, int n_in,
                              void* d_out, int out_size) {
    const float* states  = (const float*)d_in[0];
    const float* actions = (const float*)d_in[1];
    const float* conv1_w = (const float*)d_in[2];
    const float* conv1_b = (const float*)d_in[3];
    const float* ln1_g   = (const float*)d_in[4];
    const float* ln1_b   = (const float*)d_in[5];
    const float* conv2_w = (const float*)d_in[6];
    const float* conv2_b = (const float*)d_in[7];
    const float* ln2_g   = (const float*)d_in[8];
    const float* ln2_b   = (const float*)d_in[9];
    const float* conv3_w = (const float*)d_in[10];
    const float* conv3_b = (const float*)d_in[11];
    const float* ln3_g   = (const float*)d_in[12];
    const float* ln3_b   = (const float*)d_in[13];
    const float* conv4_w = (const float*)d_in[14];
    const float* conv4_b = (const float*)d_in[15];
    const float* ln4_g   = (const float*)d_in[16];
    const float* ln4_b   = (const float*)d_in[17];
    const float* fc_w    = (const float*)d_in[18];
    const float* fc_b    = (const float*)d_in[19];
    const float* gru_wih = (const float*)d_in[20];
    const float* gru_whh = (const float*)d_in[21];
    const float* gru_bih = (const float*)d_in[22];
    const float* gru_bhh = (const float*)d_in[23];
    const float* prior_w = (const float*)d_in[24];
    const float* prior_b = (const float*)d_in[25];
    const float* post_w  = (const float*)d_in[26];
    const float* post_b  = (const float*)d_in[27];
    float* out = (float*)d_out;

    auto c2 = conv_kernel<32, 32, 64, 16, 8, 2, 36, 1>;
    auto c3 = conv_kernel<64, 16, 128, 16, 8, 8, 20, 2>;
    auto c4 = conv_kernel<128, 8, 256, 16, 4, 32, 12, 3>;
    const int sm1 = (3 * 66 * 68 + 32 * 48) * 4;
    const int sm2 = (16 * 8 * 16 + 2 * (8 * 34 * 36 + 8)) * 4;
    const int sm3 = (16 * 8 * 16 + 8 * (8 * 18 * 20 + 8)) * 4;
    const int sm4 = (16 * 8 * 16 + 32 * (8 * 10 * 12 + 8)) * 4;
    const int smScan = 384 * 136 * 4;   // 208,896 B
    cudaFuncSetAttribute(conv1_kernel, cudaFuncAttributeMaxDynamicSharedMemorySize, sm1);
    cudaFuncSetAttribute(c2, cudaFuncAttributeMaxDynamicSharedMemorySize, sm2);
    cudaFuncSetAttribute(c3, cudaFuncAttributeMaxDynamicSharedMemorySize, sm3);
    cudaFuncSetAttribute(c4, cudaFuncAttributeMaxDynamicSharedMemorySize, sm4);
    cudaFuncSetAttribute(rssm_scan_kernel, cudaFuncAttributeMaxDynamicSharedMemorySize, smScan);

    init_kernel<<<32, 256>>>();
    pwt_transpose<<<512, 256>>>(post_w);
    conv1_kernel<<<1024, 256, sm1>>>(states, conv1_w, conv1_b);
    ln_silu_kernel<32 * 32 * 32, 0><<<1024, 256>>>(ln1_g, ln1_b);
    c2<<<dim3(512, 4), 256, sm2>>>(conv2_w, conv2_b);
    ln_silu_kernel<64 * 16 * 16, 1><<<1024, 256>>>(ln2_g, ln2_b);
    c3<<<dim3(128, 8), 256, sm3>>>(conv3_w, conv3_b);
    ln_silu_kernel<128 * 8 * 8, 2><<<1024, 256>>>(ln3_g, ln3_b);
    c4<<<dim3(32, 16), 256, sm4>>>(conv4_w, conv4_b);
    ln_silu_kernel<256 * 4 * 4, 3><<<1024, 256>>>(ln4_g, ln4_b);
    gemm_kernel<4096, 4096, 0><<<dim3(16, 4), 256>>>(fc_w, fc_b, nullptr, nullptr);           // feats
    gemm_kernel<256, 384, 1><<<dim3(16, 16), 256>>>(post_w + 128, post_b, nullptr, nullptr);  // fpart
    rssm_scan_kernel<<<16, 1024, smScan>>>(gru_wih, gru_whh, gru_bih, gru_bhh, actions, out);
    // prior hoisted out of the scan: prior = h_seq @ prior_w^T + prior_b
    gemm_kernel<128, 128, 2><<<dim3(16, 16), 256>>>(prior_w, prior_b, out + OUT_H, out + OUT_PRIOR);
}

// round 15
// speedup vs baseline: 1.0810x; 1.0805x over previous
#include <cuda_runtime.h>
#include <math.h>
#include <stdint.h>

#define BATCH 16
#define TT 64
#define NSAMP 1024

__device__ float d_y1[NSAMP * 32 * 32 * 32];
__device__ float d_y2[NSAMP * 64 * 16 * 16];
__device__ float d_y3[NSAMP * 128 * 8 * 8];
__device__ float d_y4[NSAMP * 256 * 4 * 4];
__device__ float d_feats[NSAMP * 256];
__device__ float d_fpart[NSAMP * 1024];
__device__ float d_stats[4][NSAMP][2];
__device__ float d_pwt[128 * 1024];   // post_w h-part, transposed k-major
__device__ float d_hbuf[2][BATCH * 128];
__device__ int   d_zidx[BATCH * 32];
__device__ int   d_bar_count[2];
__device__ volatile int d_bar_phase;

#define OUT_PRIOR 0
#define OUT_POST  1048576
#define OUT_H     2097152
#define OUT_Z     2228224

__global__ void init_kernel() {
    int i = blockIdx.x * 256 + threadIdx.x;
    if (i < 4 * NSAMP * 2) ((float*)d_stats)[i] = 0.f;
    if (i < BATCH * 128) d_hbuf[0][i] = 0.f;
}

// transpose post_w[:, 0:128] (row-major 1024x384) -> d_pwt[128][1024]
__global__ void pwt_transpose(const float* __restrict__ post_w) {
    int idx = blockIdx.x * 256 + threadIdx.x;
    if (idx >= 128 * 1024) return;
    int i = idx >> 10, row = idx & 1023;
    d_pwt[idx] = post_w[(size_t)row * 384 + i];
}

// ---------------- conv1: 3ch 64x64 -> 32ch 32x32 (PW=68, weight-swizzled) ----------------
__global__ __launch_bounds__(256) void conv1_kernel(const float* __restrict__ x,
                                                    const float* __restrict__ w,
                                                    const float* __restrict__ bias) {
    extern __shared__ float sm[];
    float* in_s = sm;                 // 3*66*68
    float* w_s  = sm + 3 * 66 * 68;   // 32*48
    int n = blockIdx.x, tid = threadIdx.x;
    for (int i = tid; i < 3 * 66 * 68; i += 256) in_s[i] = 0.f;
    for (int i = tid; i < 32 * 48; i += 256) {
        int oc = i / 48, r = i % 48;
        int pos = oc * 48 + (r & ~15) + ((((r >> 2) ^ (oc >> 2)) & 3) << 2) + (r & 3);
        w_s[pos] = w[i];
    }
    __syncthreads();
    for (int i = tid; i < 3 * 64 * 64; i += 256) {
        int c = i >> 12, r = i & 4095, y = r >> 6, xx = r & 63;
        in_s[(c * 66 + y + 1) * 68 + xx + 1] = x[(size_t)n * 12288 + i];
    }
    __syncthreads();
    float s_sum = 0.f, s_sq = 0.f;
    int ocg = tid & 7, qb = tid >> 3;
    int swz = ocg & 3;
#pragma unroll 1
    for (int qi = 0; qi < 8; qi++) {
        int q = qb + qi * 32;
        int oy = q >> 3, ox0 = (q & 7) << 2;
        float acc[16];
#pragma unroll
        for (int i = 0; i < 16; i++) acc[i] = 0.f;
#pragma unroll
        for (int c = 0; c < 3; c++)
#pragma unroll
            for (int ky = 0; ky < 4; ky++) {
                const float4* xp = (const float4*)(in_s + (c * 66 + oy * 2 + ky) * 68 + ox0 * 2);
                float xr[12];
                *(float4*)&xr[0] = xp[0];
                *(float4*)&xr[4] = xp[1];
                *(float4*)&xr[8] = xp[2];
                int kys = (ky ^ swz) << 2;
#pragma unroll
                for (int o = 0; o < 4; o++) {
                    float4 wv = *(const float4*)(w_s + (ocg * 4 + o) * 48 + c * 16 + kys);
#pragma unroll
                    for (int m = 0; m < 4; m++)
                        acc[o * 4 + m] += wv.x * xr[2 * m] + wv.y * xr[2 * m + 1]
                                        + wv.z * xr[2 * m + 2] + wv.w * xr[2 * m + 3];
                }
            }
#pragma unroll
        for (int o = 0; o < 4; o++) {
            int oc = ocg * 4 + o;
            float bv = __ldg(&bias[oc]);
#pragma unroll
            for (int m = 0; m < 4; m++) {
                float v = acc[o * 4 + m] + bv;
                d_y1[(((size_t)n * 32 + oc) * 32 + oy) * 32 + ox0 + m] = v;
                s_sum += v; s_sq += v * v;
            }
        }
    }
    for (int off = 16; off; off >>= 1) {
        s_sum += __shfl_down_sync(0xffffffffu, s_sum, off);
        s_sq  += __shfl_down_sync(0xffffffffu, s_sq, off);
    }
    if ((tid & 31) == 0) {
        atomicAdd(&d_stats[0][n][0], s_sum);
        atomicAdd(&d_stats[0][n][1], s_sq);
    }
}

// ---------------- generic conv (stages 1..3): PX-wide register tiles ----------------
template <int STAGE> __device__ __forceinline__ const float* conv_in() {
    if constexpr (STAGE == 1) return d_y1; else if constexpr (STAGE == 2) return d_y2; else return d_y3;
}
template <int STAGE> __device__ __forceinline__ float* conv_out() {
    if constexpr (STAGE == 1) return d_y2; else if constexpr (STAGE == 2) return d_y3; else return d_y4;
}

template <int CIN, int H, int COUT, int OCB, int PX, int NS, int PW, int STAGE>
__global__ __launch_bounds__(256) void conv_kernel(const float* __restrict__ w,
                                                   const float* __restrict__ bias) {
    constexpr int W = H, OH = H / 2, OW = H / 2, PH = H + 2;
    constexpr int TO = 32 / PX;
    constexpr int OCG = OCB / TO;
    constexpr int QN = OH * OW / PX;
    constexpr int CHSTRIDE = 8 * PH * PW + 8;
    constexpr int WCH = OCB * 8 * 16;
    constexpr int NROWS = NS * 8 * PH;
    extern __shared__ float sm[];
    float* w_s = sm;
    float* in_s = sm + WCH;
    const float* xin = conv_in<STAGE>();
    float* yout = conv_out<STAGE>();
    int tid = threadIdx.x;
    int n0 = blockIdx.x * NS;
    int oc0 = blockIdx.y * OCB;

    int smp = tid / (OCG * QN);
    int rem = tid % (OCG * QN);
    int ocg = rem % OCG;
    int qn = rem / OCG;
    int oy = qn / (OW / PX);
    int ox0 = (qn % (OW / PX)) * PX;
    int n = n0 + smp;

    float acc[32];
#pragma unroll
    for (int i = 0; i < 32; i++) acc[i] = 0.f;

    for (int icb = 0; icb < CIN / 8; icb++) {
        __syncthreads();
        for (int i = tid; i < WCH; i += 256) {
            int r = i & 127;
            int pos = (i & ~15) | ((((i >> 2) ^ (i >> 9)) & 3) << 2) | (i & 3);
            w_s[pos] = w[(size_t)(oc0 + (i >> 7)) * CIN * 16 + icb * 128 + r];
        }
        for (int r = tid; r < NROWS; r += 256) {
            int s = r / (8 * PH);
            int rem2 = r - s * (8 * PH);
            int c = rem2 / PH;
            int y = rem2 - c * PH;
            float* base = in_s + s * CHSTRIDE + (c * PH + y) * PW;
            if (y == 0 || y == PH - 1) {
#pragma unroll
                for (int j = 0; j < PW; j++) base[j] = 0.f;
            } else {
                base[0] = 0.f;
#pragma unroll
                for (int j = W + 1; j < PW; j++) base[j] = 0.f;
                const float4* src = (const float4*)(xin +
                    (((size_t)(n0 + s) * CIN + icb * 8 + c) * H + (y - 1)) * W);
#pragma unroll
                for (int j = 0; j < W / 4; j++) {
                    float4 v = __ldg(src + j);
                    base[1 + 4 * j] = v.x; base[2 + 4 * j] = v.y;
                    base[3 + 4 * j] = v.z; base[4 + 4 * j] = v.w;
                }
            }
        }
        __syncthreads();
#pragma unroll
        for (int icl = 0; icl < 8; icl++) {
            const float* inc = in_s + smp * CHSTRIDE + icl * PH * PW;
            const float* wb = w_s + icl * 16;
#pragma unroll
            for (int ky = 0; ky < 4; ky++) {
                const float4* xp = (const float4*)(inc + (oy * 2 + ky) * PW + ox0 * 2);
                float xr[2 * PX + 4];
#pragma unroll
                for (int f = 0; f < PX / 2 + 1; f++) *(float4*)&xr[4 * f] = xp[f];
#pragma unroll
                for (int o = 0; o < TO; o++) {
                    int ol = ocg * TO + o;
                    float4 wv = *(const float4*)(wb + ol * 128 + ((ky ^ ((ol >> 2) & 3)) << 2));
#pragma unroll
                    for (int m = 0; m < PX; m++)
                        acc[o * PX + m] += wv.x * xr[2 * m] + wv.y * xr[2 * m + 1]
                                         + wv.z * xr[2 * m + 2] + wv.w * xr[2 * m + 3];
                }
            }
        }
    }
    float s_sum = 0.f, s_sq = 0.f;
#pragma unroll
    for (int o = 0; o < TO; o++) {
        int oc = oc0 + ocg * TO + o;
        float bv = __ldg(&bias[oc]);
#pragma unroll
        for (int m = 0; m < PX; m++) {
            float v = acc[o * PX + m] + bv;
            yout[(((size_t)n * COUT + oc) * OH + oy) * OW + ox0 + m] = v;
            s_sum += v; s_sq += v * v;
        }
    }
    constexpr int RW = (OCG * QN >= 32) ? 32 : (OCG * QN);
    for (int off = RW / 2; off; off >>= 1) {
        s_sum += __shfl_down_sync(0xffffffffu, s_sum, off, RW);
        s_sq  += __shfl_down_sync(0xffffffffu, s_sq, off, RW);
    }
    if ((tid % RW) == 0) {
        atomicAdd(&d_stats[STAGE][n][0], s_sum);
        atomicAdd(&d_stats[STAGE][n][1], s_sq);
    }
}

// ---------------- LayerNorm + SiLU (vectorized) ----------------
template <int CHW, int STAGE>
__global__ void ln_silu_kernel(const float* __restrict__ g, const float* __restrict__ bp) {
    float* y;
    if constexpr (STAGE == 0) y = d_y1;
    else if constexpr (STAGE == 1) y = d_y2;
    else if constexpr (STAGE == 2) y = d_y3;
    else y = d_y4;
    int n = blockIdx.x;
    float mean = d_stats[STAGE][n][0] * (1.f / CHW);
    float var = d_stats[STAGE][n][1] * (1.f / CHW) - mean * mean;
    float inv = rsqrtf(var + 1e-5f);
    float4* yp = (float4*)(y + (size_t)n * CHW);
    const float4* gp = (const float4*)g;
    const float4* bpp = (const float4*)bp;
    for (int i = threadIdx.x; i < CHW / 4; i += blockDim.x) {
        float4 v4 = yp[i], g4 = __ldg(gp + i), b4 = __ldg(bpp + i);
        float a0 = (v4.x - mean) * inv * g4.x + b4.x;
        float a1 = (v4.y - mean) * inv * g4.y + b4.y;
        float a2 = (v4.z - mean) * inv * g4.z + b4.z;
        float a3 = (v4.w - mean) * inv * g4.w + b4.w;
        v4.x = a0 / (1.f + __expf(-a0));
        v4.y = a1 / (1.f + __expf(-a1));
        v4.z = a2 / (1.f + __expf(-a2));
        v4.w = a3 / (1.f + __expf(-a3));
        yp[i] = v4;
    }
}

// ---------------- SGEMM: C[M,N] = A[M,K] * B[N,:K]^T + bias ----------------
// WHICH=0: A=d_y4 -> C=d_feats. WHICH=1: A=d_feats -> C=d_fpart. WHICH=2: ext ptrs.
template <int KK, int LDB, int WHICH>
__global__ __launch_bounds__(256) void gemm_kernel(const float* __restrict__ Bmat,
                                                   const float* __restrict__ bias,
                                                   const float* __restrict__ Aext,
                                                   float* __restrict__ Cext) {
    const float* A = (WHICH == 0) ? d_y4 : (WHICH == 1) ? d_feats : Aext;
    float* C = (WHICH == 0) ? d_feats : (WHICH == 1) ? d_fpart : Cext;
    const int ldc = gridDim.y * 64;
    __shared__ float As[16][68];
    __shared__ float Bs[16][68];
    int m0 = blockIdx.x * 64, n0 = blockIdx.y * 64;
    int tid = threadIdx.x;
    int tx = tid % 16, ty = tid / 16;
    float acc[16];
#pragma unroll
    for (int i = 0; i < 16; i++) acc[i] = 0.f;
    for (int k0 = 0; k0 < KK; k0 += 16) {
#pragma unroll
        for (int e = 0; e < 4; e++) {
            int f = tid + e * 256;
            int m = f >> 4, k = f & 15;
            As[k][m] = A[(size_t)(m0 + m) * KK + k0 + k];
            Bs[k][m] = Bmat[(size_t)(n0 + m) * LDB + k0 + k];
        }
        __syncthreads();
#pragma unroll
        for (int k = 0; k < 16; k++) {
            float4 a4 = *(const float4*)&As[k][ty * 4];
            float4 b4 = *(const float4*)&Bs[k][tx * 4];
            acc[0]  += a4.x * b4.x; acc[1]  += a4.x * b4.y; acc[2]  += a4.x * b4.z; acc[3]  += a4.x * b4.w;
            acc[4]  += a4.y * b4.x; acc[5]  += a4.y * b4.y; acc[6]  += a4.y * b4.z; acc[7]  += a4.y * b4.w;
            acc[8]  += a4.z * b4.x; acc[9]  += a4.z * b4.y; acc[10] += a4.z * b4.z; acc[11] += a4.z * b4.w;
            acc[12] += a4.w * b4.x; acc[13] += a4.w * b4.y; acc[14] += a4.w * b4.z; acc[15] += a4.w * b4.w;
        }
        __syncthreads();
    }
#pragma unroll
    for (int i = 0; i < 4; i++)
#pragma unroll
        for (int j = 0; j < 4; j++)
            C[(size_t)(m0 + ty * 4 + i) * ldc + n0 + tx * 4 + j] =
                acc[i * 4 + j] + __ldg(&bias[n0 + tx * 4 + j]);
}

// ---------------- persistent GRU scan (64 blocks, grid barriers — R6 structure) ----------------
// Changes vs R6: prior hoisted out (post-scan GEMM); stage B uses transposed d_pwt
// (coalesced: 1 line/warp/load instead of 32).
__device__ __forceinline__ void grid_bar(int parity) {
    __threadfence();
    __syncthreads();
    if (threadIdx.x == 0) {
        int phase = d_bar_phase;
        int a = atomicAdd(&d_bar_count[parity], 1);
        if (a == 63) {
            d_bar_count[parity] = 0;
            __threadfence();
            d_bar_phase = phase + 1;
        } else {
            while (d_bar_phase == phase) { __nanosleep(20); }
        }
    }
    __syncthreads();
}

__global__ __launch_bounds__(256) void rssm_scan_kernel(
    const float* __restrict__ wih, const float* __restrict__ whh,
    const float* __restrict__ bih, const float* __restrict__ bhh,
    const float* __restrict__ actions, float* __restrict__ out) {
    int tid = threadIdx.x;
    int blk = blockIdx.x;
    int b = blk >> 2;
    int sub = blk & 3;
    __shared__ __align__(16) float h_s[128];
    __shared__ int zidx_s[32];
    __shared__ float act_s[8];

    for (int t = 0; t < TT; t++) {
        int p = t & 1;
        // ---- stage A: gates + h_new (each block owns 32 hidden units) ----
        if (tid < 128) h_s[tid] = __ldcg(&d_hbuf[p][b * 128 + tid]);
        if (tid < 32 && t > 0) zidx_s[tid] = __ldcg(&d_zidx[b * 32 + tid]);
        if (tid < 6) act_s[tid] = __ldg(&actions[(b * TT + t) * 6 + tid]);
        __syncthreads();
        {
            int grp = tid >> 3, l = tid & 7;
            int j = sub * 32 + grp;
            const float* whh_r = whh + (size_t)j * 128;
            const float* whh_z = whh + (size_t)(j + 128) * 128;
            const float* whh_n = whh + (size_t)(j + 256) * 128;
            float ar = 0.f, az = 0.f, ani = 0.f, anh = 0.f;
#pragma unroll
            for (int i = 0; i < 16; i++) {
                int k = l + i * 8;
                float h = h_s[k];
                ar  += h * __ldg(&whh_r[k]);
                az  += h * __ldg(&whh_z[k]);
                anh += h * __ldg(&whh_n[k]);
            }
            const float* wih_r = wih + (size_t)j * 1030;
            const float* wih_z = wih + (size_t)(j + 128) * 1030;
            const float* wih_n = wih + (size_t)(j + 256) * 1030;
            if (t > 0) {
                for (int c = l; c < 32; c += 8) {
                    int col = c * 32 + zidx_s[c];
                    ar  += __ldg(&wih_r[col]);
                    az  += __ldg(&wih_z[col]);
                    ani += __ldg(&wih_n[col]);
                }
            }
            if (l < 6) {
                float a = act_s[l];
                int col = 1024 + l;
                ar  += a * __ldg(&wih_r[col]);
                az  += a * __ldg(&wih_z[col]);
                ani += a * __ldg(&wih_n[col]);
            }
            for (int off = 4; off; off >>= 1) {
                ar  += __shfl_down_sync(0xffffffffu, ar, off, 8);
                az  += __shfl_down_sync(0xffffffffu, az, off, 8);
                ani += __shfl_down_sync(0xffffffffu, ani, off, 8);
                anh += __shfl_down_sync(0xffffffffu, anh, off, 8);
            }
            if (l == 0) {
                float r = 1.f / (1.f + expf(-(ar + __ldg(&bih[j]) + __ldg(&bhh[j]))));
                float u = 1.f / (1.f + expf(-(az + __ldg(&bih[j + 128]) + __ldg(&bhh[j + 128]))));
                float nn = tanhf(ani + __ldg(&bih[j + 256]) + r * (anh + __ldg(&bhh[j + 256])));
                float hn = (1.f - u) * nn + u * h_s[j];
                d_hbuf[p ^ 1][b * 128 + j] = hn;
                out[OUT_H + (size_t)(b * TT + t) * 128 + j] = hn;
            }
        }
        grid_bar(0);
        // ---- stage B: post logits + argmax (each block owns 8 categoricals) ----
        if (tid < 128) h_s[tid] = __ldcg(&d_hbuf[p ^ 1][b * 128 + tid]);
        __syncthreads();
        {
            int warp = tid >> 5, lane = tid & 31;
            int c = sub * 8 + warp;
            int row = c * 32 + lane;
            float aq = __ldg(&d_fpart[(size_t)(b * TT + t) * 1024 + row]);  // feats part + post_b
#pragma unroll 16
            for (int i = 0; i < 128; i++)
                aq += h_s[i] * __ldg(&d_pwt[(i << 10) + row]);
            size_t n_idx = (size_t)(b * TT + t) * 1024 + row;
            out[OUT_POST + n_idx] = aq;
            float bv = aq; int bi = lane;
#pragma unroll
            for (int off = 16; off; off >>= 1) {
                float ov = __shfl_xor_sync(0xffffffffu, bv, off);
                int oi = __shfl_xor_sync(0xffffffffu, bi, off);
                if (ov > bv || (ov == bv && oi < bi)) { bv = ov; bi = oi; }
            }
            out[OUT_Z + n_idx] = (lane == bi) ? 1.f : 0.f;
            if (lane == 0) d_zidx[b * 32 + c] = bi;
        }
        grid_bar(1);
    }
}

// ---------------- host launch ----------------
extern "C" void kernel_launch(void* const* d_in, const int* in_sizes, int n_in,
                              void* d_out, int out_size) {
    const float* states  = (const float*)d_in[0];
    const float* actions = (const float*)d_in[1];
    const float* conv1_w = (const float*)d_in[2];
    const float* conv1_b = (const float*)d_in[3];
    const float* ln1_g   = (const float*)d_in[4];
    const float* ln1_b   = (const float*)d_in[5];
    const float* conv2_w = (const float*)d_in[6];
    const float* conv2_b = (const float*)d_in[7];
    const float* ln2_g   = (const float*)d_in[8];
    const float* ln2_b   = (const float*)d_in[9];
    const float* conv3_w = (const float*)d_in[10];
    const float* conv3_b = (const float*)d_in[11];
    const float* ln3_g   = (const float*)d_in[12];
    const float* ln3_b   = (const float*)d_in[13];
    const float* conv4_w = (const float*)d_in[14];
    const float* conv4_b = (const float*)d_in[15];
    const float* ln4_g   = (const float*)d_in[16];
    const float* ln4_b   = (const float*)d_in[17];
    const float* fc_w    = (const float*)d_in[18];
    const float* fc_b    = (const float*)d_in[19];
    const float* gru_wih = (const float*)d_in[20];
    const float* gru_whh = (const float*)d_in[21];
    const float* gru_bih = (const float*)d_in[22];
    const float* gru_bhh = (const float*)d_in[23];
    const float* prior_w = (const float*)d_in[24];
    const float* prior_b = (const float*)d_in[25];
    const float* post_w  = (const float*)d_in[26];
    const float* post_b  = (const float*)d_in[27];
    float* out = (float*)d_out;

    auto c2 = conv_kernel<32, 32, 64, 16, 8, 2, 36, 1>;
    auto c3 = conv_kernel<64, 16, 128, 16, 8, 8, 20, 2>;
    auto c4 = conv_kernel<128, 8, 256, 16, 4, 32, 12, 3>;
    const int sm1 = (3 * 66 * 68 + 32 * 48) * 4;
    const int sm2 = (16 * 8 * 16 + 2 * (8 * 34 * 36 + 8)) * 4;
    const int sm3 = (16 * 8 * 16 + 8 * (8 * 18 * 20 + 8)) * 4;
    const int sm4 = (16 * 8 * 16 + 32 * (8 * 10 * 12 + 8)) * 4;
    cudaFuncSetAttribute(conv1_kernel, cudaFuncAttributeMaxDynamicSharedMemorySize, sm1);
    cudaFuncSetAttribute(c2, cudaFuncAttributeMaxDynamicSharedMemorySize, sm2);
    cudaFuncSetAttribute(c3, cudaFuncAttributeMaxDynamicSharedMemorySize, sm3);
    cudaFuncSetAttribute(c4, cudaFuncAttributeMaxDynamicSharedMemorySize, sm4);

    init_kernel<<<32, 256>>>();
    pwt_transpose<<<512, 256>>>(post_w);
    conv1_kernel<<<1024, 256, sm1>>>(states, conv1_w, conv1_b);
    ln_silu_kernel<32 * 32 * 32, 0><<<1024, 256>>>(ln1_g, ln1_b);
    c2<<<dim3(512, 4), 256, sm2>>>(conv2_w, conv2_b);
    ln_silu_kernel<64 * 16 * 16, 1><<<1024, 256>>>(ln2_g, ln2_b);
    c3<<<dim3(128, 8), 256, sm3>>>(conv3_w, conv3_b);
    ln_silu_kernel<128 * 8 * 8, 2><<<1024, 256>>>(ln3_g, ln3_b);
    c4<<<dim3(32, 16), 256, sm4>>>(conv4_w, conv4_b);
    ln_silu_kernel<256 * 4 * 4, 3><<<1024, 256>>>(ln4_g, ln4_b);
    gemm_kernel<4096, 4096, 0><<<dim3(16, 4), 256>>>(fc_w, fc_b, nullptr, nullptr);           // feats
    gemm_kernel<256, 384, 1><<<dim3(16, 16), 256>>>(post_w + 128, post_b, nullptr, nullptr);  // fpart
    rssm_scan_kernel<<<64, 256>>>(gru_wih, gru_whh, gru_bih, gru_bhh, actions, out);
    // prior hoisted out of the scan: prior = h_seq @ prior_w^T + prior_b
    gemm_kernel<128, 128, 2><<<dim3(16, 16), 256>>>(prior_w, prior_b, out + OUT_H, out + OUT_PRIOR);
}

// round 16
// speedup vs baseline: 1.2918x; 1.1949x over previous
#include <cuda_runtime.h>
#include <math.h>
#include <stdint.h>

#define BATCH 16
#define TT 64
#define NSAMP 1024

__device__ float d_y1[NSAMP * 32 * 32 * 32];
__device__ float d_y2[NSAMP * 64 * 16 * 16];
__device__ float d_y3[NSAMP * 128 * 8 * 8];
__device__ float d_y4[NSAMP * 256 * 4 * 4];
__device__ float d_feats[NSAMP * 256];
__device__ float d_fpart[NSAMP * 1024];
__device__ float d_stats[4][NSAMP][2];
__device__ float d_hbuf[2][BATCH * 128];
__device__ int   d_zidx[BATCH * 32];
__device__ int   d_bar_count[2];
__device__ volatile int d_bar_phase;

#define OUT_PRIOR 0
#define OUT_POST  1048576
#define OUT_H     2097152
#define OUT_Z     2228224

__global__ void init_kernel() {
    int i = blockIdx.x * 256 + threadIdx.x;
    if (i < 4 * NSAMP * 2) ((float*)d_stats)[i] = 0.f;
    if (i < BATCH * 128) d_hbuf[0][i] = 0.f;
}

// ---------------- conv1: 3ch 64x64 -> 32ch 32x32 (PW=68, weight-swizzled) ----------------
__global__ __launch_bounds__(256) void conv1_kernel(const float* __restrict__ x,
                                                    const float* __restrict__ w,
                                                    const float* __restrict__ bias) {
    extern __shared__ float sm[];
    float* in_s = sm;                 // 3*66*68
    float* w_s  = sm + 3 * 66 * 68;   // 32*48
    int n = blockIdx.x, tid = threadIdx.x;
    for (int i = tid; i < 3 * 66 * 68; i += 256) in_s[i] = 0.f;
    for (int i = tid; i < 32 * 48; i += 256) {
        int oc = i / 48, r = i % 48;
        int pos = oc * 48 + (r & ~15) + ((((r >> 2) ^ (oc >> 2)) & 3) << 2) + (r & 3);
        w_s[pos] = w[i];
    }
    __syncthreads();
    for (int i = tid; i < 3 * 64 * 64; i += 256) {
        int c = i >> 12, r = i & 4095, y = r >> 6, xx = r & 63;
        in_s[(c * 66 + y + 1) * 68 + xx + 1] = x[(size_t)n * 12288 + i];
    }
    __syncthreads();
    float s_sum = 0.f, s_sq = 0.f;
    int ocg = tid & 7, qb = tid >> 3;
    int swz = ocg & 3;
#pragma unroll 1
    for (int qi = 0; qi < 8; qi++) {
        int q = qb + qi * 32;
        int oy = q >> 3, ox0 = (q & 7) << 2;
        float acc[16];
#pragma unroll
        for (int i = 0; i < 16; i++) acc[i] = 0.f;
#pragma unroll
        for (int c = 0; c < 3; c++)
#pragma unroll
            for (int ky = 0; ky < 4; ky++) {
                const float4* xp = (const float4*)(in_s + (c * 66 + oy * 2 + ky) * 68 + ox0 * 2);
                float xr[12];
                *(float4*)&xr[0] = xp[0];
                *(float4*)&xr[4] = xp[1];
                *(float4*)&xr[8] = xp[2];
                int kys = (ky ^ swz) << 2;
#pragma unroll
                for (int o = 0; o < 4; o++) {
                    float4 wv = *(const float4*)(w_s + (ocg * 4 + o) * 48 + c * 16 + kys);
#pragma unroll
                    for (int m = 0; m < 4; m++)
                        acc[o * 4 + m] += wv.x * xr[2 * m] + wv.y * xr[2 * m + 1]
                                        + wv.z * xr[2 * m + 2] + wv.w * xr[2 * m + 3];
                }
            }
#pragma unroll
        for (int o = 0; o < 4; o++) {
            int oc = ocg * 4 + o;
            float bv = __ldg(&bias[oc]);
#pragma unroll
            for (int m = 0; m < 4; m++) {
                float v = acc[o * 4 + m] + bv;
                d_y1[(((size_t)n * 32 + oc) * 32 + oy) * 32 + ox0 + m] = v;
                s_sum += v; s_sq += v * v;
            }
        }
    }
    for (int off = 16; off; off >>= 1) {
        s_sum += __shfl_down_sync(0xffffffffu, s_sum, off);
        s_sq  += __shfl_down_sync(0xffffffffu, s_sq, off);
    }
    if ((tid & 31) == 0) {
        atomicAdd(&d_stats[0][n][0], s_sum);
        atomicAdd(&d_stats[0][n][1], s_sq);
    }
}

// ---------------- generic conv (stages 1..3): PX-wide register tiles ----------------
template <int STAGE> __device__ __forceinline__ const float* conv_in() {
    if constexpr (STAGE == 1) return d_y1; else if constexpr (STAGE == 2) return d_y2; else return d_y3;
}
template <int STAGE> __device__ __forceinline__ float* conv_out() {
    if constexpr (STAGE == 1) return d_y2; else if constexpr (STAGE == 2) return d_y3; else return d_y4;
}

template <int CIN, int H, int COUT, int OCB, int PX, int NS, int PW, int STAGE>
__global__ __launch_bounds__(256) void conv_kernel(const float* __restrict__ w,
                                                   const float* __restrict__ bias) {
    constexpr int W = H, OH = H / 2, OW = H / 2, PH = H + 2;
    constexpr int TO = 32 / PX;
    constexpr int OCG = OCB / TO;
    constexpr int QN = OH * OW / PX;
    constexpr int CHSTRIDE = 8 * PH * PW + 8;
    constexpr int WCH = OCB * 8 * 16;
    constexpr int NROWS = NS * 8 * PH;
    extern __shared__ float sm[];
    float* w_s = sm;
    float* in_s = sm + WCH;
    const float* xin = conv_in<STAGE>();
    float* yout = conv_out<STAGE>();
    int tid = threadIdx.x;
    int n0 = blockIdx.x * NS;
    int oc0 = blockIdx.y * OCB;

    int smp = tid / (OCG * QN);
    int rem = tid % (OCG * QN);
    int ocg = rem % OCG;
    int qn = rem / OCG;
    int oy = qn / (OW / PX);
    int ox0 = (qn % (OW / PX)) * PX;
    int n = n0 + smp;

    float acc[32];
#pragma unroll
    for (int i = 0; i < 32; i++) acc[i] = 0.f;

    for (int icb = 0; icb < CIN / 8; icb++) {
        __syncthreads();
        for (int i = tid; i < WCH; i += 256) {
            int r = i & 127;
            int pos = (i & ~15) | ((((i >> 2) ^ (i >> 9)) & 3) << 2) | (i & 3);
            w_s[pos] = w[(size_t)(oc0 + (i >> 7)) * CIN * 16 + icb * 128 + r];
        }
        for (int r = tid; r < NROWS; r += 256) {
            int s = r / (8 * PH);
            int rem2 = r - s * (8 * PH);
            int c = rem2 / PH;
            int y = rem2 - c * PH;
            float* base = in_s + s * CHSTRIDE + (c * PH + y) * PW;
            if (y == 0 || y == PH - 1) {
#pragma unroll
                for (int j = 0; j < PW; j++) base[j] = 0.f;
            } else {
                base[0] = 0.f;
#pragma unroll
                for (int j = W + 1; j < PW; j++) base[j] = 0.f;
                const float4* src = (const float4*)(xin +
                    (((size_t)(n0 + s) * CIN + icb * 8 + c) * H + (y - 1)) * W);
#pragma unroll
                for (int j = 0; j < W / 4; j++) {
                    float4 v = __ldg(src + j);
                    base[1 + 4 * j] = v.x; base[2 + 4 * j] = v.y;
                    base[3 + 4 * j] = v.z; base[4 + 4 * j] = v.w;
                }
            }
        }
        __syncthreads();
#pragma unroll
        for (int icl = 0; icl < 8; icl++) {
            const float* inc = in_s + smp * CHSTRIDE + icl * PH * PW;
            const float* wb = w_s + icl * 16;
#pragma unroll
            for (int ky = 0; ky < 4; ky++) {
                const float4* xp = (const float4*)(inc + (oy * 2 + ky) * PW + ox0 * 2);
                float xr[2 * PX + 4];
#pragma unroll
                for (int f = 0; f < PX / 2 + 1; f++) *(float4*)&xr[4 * f] = xp[f];
#pragma unroll
                for (int o = 0; o < TO; o++) {
                    int ol = ocg * TO + o;
                    float4 wv = *(const float4*)(wb + ol * 128 + ((ky ^ ((ol >> 2) & 3)) << 2));
#pragma unroll
                    for (int m = 0; m < PX; m++)
                        acc[o * PX + m] += wv.x * xr[2 * m] + wv.y * xr[2 * m + 1]
                                         + wv.z * xr[2 * m + 2] + wv.w * xr[2 * m + 3];
                }
            }
        }
    }
    float s_sum = 0.f, s_sq = 0.f;
#pragma unroll
    for (int o = 0; o < TO; o++) {
        int oc = oc0 + ocg * TO + o;
        float bv = __ldg(&bias[oc]);
#pragma unroll
        for (int m = 0; m < PX; m++) {
            float v = acc[o * PX + m] + bv;
            yout[(((size_t)n * COUT + oc) * OH + oy) * OW + ox0 + m] = v;
            s_sum += v; s_sq += v * v;
        }
    }
    constexpr int RW = (OCG * QN >= 32) ? 32 : (OCG * QN);
    for (int off = RW / 2; off; off >>= 1) {
        s_sum += __shfl_down_sync(0xffffffffu, s_sum, off, RW);
        s_sq  += __shfl_down_sync(0xffffffffu, s_sq, off, RW);
    }
    if ((tid % RW) == 0) {
        atomicAdd(&d_stats[STAGE][n][0], s_sum);
        atomicAdd(&d_stats[STAGE][n][1], s_sq);
    }
}

// ---------------- LayerNorm + SiLU (vectorized) ----------------
template <int CHW, int STAGE>
__global__ void ln_silu_kernel(const float* __restrict__ g, const float* __restrict__ bp) {
    float* y;
    if constexpr (STAGE == 0) y = d_y1;
    else if constexpr (STAGE == 1) y = d_y2;
    else if constexpr (STAGE == 2) y = d_y3;
    else y = d_y4;
    int n = blockIdx.x;
    float mean = d_stats[STAGE][n][0] * (1.f / CHW);
    float var = d_stats[STAGE][n][1] * (1.f / CHW) - mean * mean;
    float inv = rsqrtf(var + 1e-5f);
    float4* yp = (float4*)(y + (size_t)n * CHW);
    const float4* gp = (const float4*)g;
    const float4* bpp = (const float4*)bp;
    for (int i = threadIdx.x; i < CHW / 4; i += blockDim.x) {
        float4 v4 = yp[i], g4 = __ldg(gp + i), b4 = __ldg(bpp + i);
        float a0 = (v4.x - mean) * inv * g4.x + b4.x;
        float a1 = (v4.y - mean) * inv * g4.y + b4.y;
        float a2 = (v4.z - mean) * inv * g4.z + b4.z;
        float a3 = (v4.w - mean) * inv * g4.w + b4.w;
        v4.x = a0 / (1.f + __expf(-a0));
        v4.y = a1 / (1.f + __expf(-a1));
        v4.z = a2 / (1.f + __expf(-a2));
        v4.w = a3 / (1.f + __expf(-a3));
        yp[i] = v4;
    }
}

// ---------------- SGEMM: C[M,N] = A[M,K] * B[N,:K]^T + bias ----------------
// WHICH=0: A=d_y4 -> C=d_feats. WHICH=1: A=d_feats -> C=d_fpart. WHICH=2: ext ptrs.
template <int KK, int LDB, int WHICH>
__global__ __launch_bounds__(256) void gemm_kernel(const float* __restrict__ Bmat,
                                                   const float* __restrict__ bias,
                                                   const float* __restrict__ Aext,
                                                   float* __restrict__ Cext) {
    const float* A = (WHICH == 0) ? d_y4 : (WHICH == 1) ? d_feats : Aext;
    float* C = (WHICH == 0) ? d_feats : (WHICH == 1) ? d_fpart : Cext;
    const int ldc = gridDim.y * 64;
    __shared__ float As[16][68];
    __shared__ float Bs[16][68];
    int m0 = blockIdx.x * 64, n0 = blockIdx.y * 64;
    int tid = threadIdx.x;
    int tx = tid % 16, ty = tid / 16;
    float acc[16];
#pragma unroll
    for (int i = 0; i < 16; i++) acc[i] = 0.f;
    for (int k0 = 0; k0 < KK; k0 += 16) {
#pragma unroll
        for (int e = 0; e < 4; e++) {
            int f = tid + e * 256;
            int m = f >> 4, k = f & 15;
            As[k][m] = A[(size_t)(m0 + m) * KK + k0 + k];
            Bs[k][m] = Bmat[(size_t)(n0 + m) * LDB + k0 + k];
        }
        __syncthreads();
#pragma unroll
        for (int k = 0; k < 16; k++) {
            float4 a4 = *(const float4*)&As[k][ty * 4];
            float4 b4 = *(const float4*)&Bs[k][tx * 4];
            acc[0]  += a4.x * b4.x; acc[1]  += a4.x * b4.y; acc[2]  += a4.x * b4.z; acc[3]  += a4.x * b4.w;
            acc[4]  += a4.y * b4.x; acc[5]  += a4.y * b4.y; acc[6]  += a4.y * b4.z; acc[7]  += a4.y * b4.w;
            acc[8]  += a4.z * b4.x; acc[9]  += a4.z * b4.y; acc[10] += a4.z * b4.z; acc[11] += a4.z * b4.w;
            acc[12] += a4.w * b4.x; acc[13] += a4.w * b4.y; acc[14] += a4.w * b4.z; acc[15] += a4.w * b4.w;
        }
        __syncthreads();
    }
#pragma unroll
    for (int i = 0; i < 4; i++)
#pragma unroll
        for (int j = 0; j < 4; j++)
            C[(size_t)(m0 + ty * 4 + i) * ldc + n0 + tx * 4 + j] =
                acc[i * 4 + j] + __ldg(&bias[n0 + tx * 4 + j]);
}

// ---------------- persistent GRU scan (EXACT R6 structure; only prior removed) ----------------
__device__ __forceinline__ void grid_bar(int parity) {
    __threadfence();
    __syncthreads();
    if (threadIdx.x == 0) {
        int phase = d_bar_phase;
        int a = atomicAdd(&d_bar_count[parity], 1);
        if (a == 63) {
            d_bar_count[parity] = 0;
            __threadfence();
            d_bar_phase = phase + 1;
        } else {
            while (d_bar_phase == phase) { __nanosleep(20); }
        }
    }
    __syncthreads();
}

__global__ __launch_bounds__(256) void rssm_scan_kernel(
    const float* __restrict__ wih, const float* __restrict__ whh,
    const float* __restrict__ bih, const float* __restrict__ bhh,
    const float* __restrict__ post_w, const float* __restrict__ actions,
    float* __restrict__ out) {
    int tid = threadIdx.x;
    int blk = blockIdx.x;
    int b = blk >> 2;
    int sub = blk & 3;
    __shared__ __align__(16) float h_s[128];
    __shared__ int zidx_s[32];
    __shared__ float act_s[8];

    for (int t = 0; t < TT; t++) {
        int p = t & 1;
        // ---- stage A: gates + h_new (each block owns 32 hidden units) ----
        if (tid < 128) h_s[tid] = __ldcg(&d_hbuf[p][b * 128 + tid]);
        if (tid < 32 && t > 0) zidx_s[tid] = __ldcg(&d_zidx[b * 32 + tid]);
        if (tid < 6) act_s[tid] = __ldg(&actions[(b * TT + t) * 6 + tid]);
        __syncthreads();
        {
            int grp = tid >> 3, l = tid & 7;
            int j = sub * 32 + grp;
            const float* whh_r = whh + (size_t)j * 128;
            const float* whh_z = whh + (size_t)(j + 128) * 128;
            const float* whh_n = whh + (size_t)(j + 256) * 128;
            float ar = 0.f, az = 0.f, ani = 0.f, anh = 0.f;
#pragma unroll
            for (int i = 0; i < 16; i++) {
                int k = l + i * 8;
                float h = h_s[k];
                ar  += h * __ldg(&whh_r[k]);
                az  += h * __ldg(&whh_z[k]);
                anh += h * __ldg(&whh_n[k]);
            }
            const float* wih_r = wih + (size_t)j * 1030;
            const float* wih_z = wih + (size_t)(j + 128) * 1030;
            const float* wih_n = wih + (size_t)(j + 256) * 1030;
            if (t > 0) {
                for (int c = l; c < 32; c += 8) {
                    int col = c * 32 + zidx_s[c];
                    ar  += __ldg(&wih_r[col]);
                    az  += __ldg(&wih_z[col]);
                    ani += __ldg(&wih_n[col]);
                }
            }
            if (l < 6) {
                float a = act_s[l];
                int col = 1024 + l;
                ar  += a * __ldg(&wih_r[col]);
                az  += a * __ldg(&wih_z[col]);
                ani += a * __ldg(&wih_n[col]);
            }
            for (int off = 4; off; off >>= 1) {
                ar  += __shfl_down_sync(0xffffffffu, ar, off, 8);
                az  += __shfl_down_sync(0xffffffffu, az, off, 8);
                ani += __shfl_down_sync(0xffffffffu, ani, off, 8);
                anh += __shfl_down_sync(0xffffffffu, anh, off, 8);
            }
            if (l == 0) {
                float r = 1.f / (1.f + expf(-(ar + __ldg(&bih[j]) + __ldg(&bhh[j]))));
                float u = 1.f / (1.f + expf(-(az + __ldg(&bih[j + 128]) + __ldg(&bhh[j + 128]))));
                float nn = tanhf(ani + __ldg(&bih[j + 256]) + r * (anh + __ldg(&bhh[j + 256])));
                float hn = (1.f - u) * nn + u * h_s[j];
                d_hbuf[p ^ 1][b * 128 + j] = hn;
                out[OUT_H + (size_t)(b * TT + t) * 128 + j] = hn;
            }
        }
        grid_bar(0);
        // ---- stage B: post logits + argmax (prior hoisted to post-scan GEMM) ----
        if (tid < 128) h_s[tid] = __ldcg(&d_hbuf[p ^ 1][b * 128 + tid]);
        __syncthreads();
        {
            int warp = tid >> 5, lane = tid & 31;
            int c = sub * 8 + warp;
            int row = c * 32 + lane;
            const float4* hp4 = (const float4*)h_s;
            const float4* qw4 = (const float4*)(post_w + (size_t)row * 384);
            float aq = 0.f;
#pragma unroll
            for (int i = 0; i < 32; i++) {
                float4 h4 = hp4[i];
                float4 v4 = __ldg(qw4 + i);
                aq += h4.x * v4.x + h4.y * v4.y + h4.z * v4.z + h4.w * v4.w;
            }
            aq += __ldg(&d_fpart[(size_t)(b * TT + t) * 1024 + row]);  // feats part + post_b
            size_t n_idx = (size_t)(b * TT + t) * 1024 + row;
            out[OUT_POST + n_idx] = aq;
            float bv = aq; int bi = lane;
#pragma unroll
            for (int off = 16; off; off >>= 1) {
                float ov = __shfl_xor_sync(0xffffffffu, bv, off);
                int oi = __shfl_xor_sync(0xffffffffu, bi, off);
                if (ov > bv || (ov == bv && oi < bi)) { bv = ov; bi = oi; }
            }
            out[OUT_Z + n_idx] = (lane == bi) ? 1.f : 0.f;
            if (lane == 0) d_zidx[b * 32 + c] = bi;
        }
        grid_bar(1);
    }
}

// ---------------- host launch ----------------
extern "C" void kernel_launch(void* const* d_in, const int* in_sizes, int n_in,
                              void* d_out, int out_size) {
    const float* states  = (const float*)d_in[0];
    const float* actions = (const float*)d_in[1];
    const float* conv1_w = (const float*)d_in[2];
    const float* conv1_b = (const float*)d_in[3];
    const float* ln1_g   = (const float*)d_in[4];
    const float* ln1_b   = (const float*)d_in[5];
    const float* conv2_w = (const float*)d_in[6];
    const float* conv2_b = (const float*)d_in[7];
    const float* ln2_g   = (const float*)d_in[8];
    const float* ln2_b   = (const float*)d_in[9];
    const float* conv3_w = (const float*)d_in[10];
    const float* conv3_b = (const float*)d_in[11];
    const float* ln3_g   = (const float*)d_in[12];
    const float* ln3_b   = (const float*)d_in[13];
    const float* conv4_w = (const float*)d_in[14];
    const float* conv4_b = (const float*)d_in[15];
    const float* ln4_g   = (const float*)d_in[16];
    const float* ln4_b   = (const float*)d_in[17];
    const float* fc_w    = (const float*)d_in[18];
    const float* fc_b    = (const float*)d_in[19];
    const float* gru_wih = (const float*)d_in[20];
    const float* gru_whh = (const float*)d_in[21];
    const float* gru_bih = (const float*)d_in[22];
    const float* gru_bhh = (const float*)d_in[23];
    const float* prior_w = (const float*)d_in[24];
    const float* prior_b = (const float*)d_in[25];
    const float* post_w  = (const float*)d_in[26];
    const float* post_b  = (const float*)d_in[27];
    float* out = (float*)d_out;

    auto c2 = conv_kernel<32, 32, 64, 16, 8, 2, 36, 1>;
    auto c3 = conv_kernel<64, 16, 128, 16, 8, 8, 20, 2>;
    auto c4 = conv_kernel<128, 8, 256, 16, 4, 32, 12, 3>;
    const int sm1 = (3 * 66 * 68 + 32 * 48) * 4;
    const int sm2 = (16 * 8 * 16 + 2 * (8 * 34 * 36 + 8)) * 4;
    const int sm3 = (16 * 8 * 16 + 8 * (8 * 18 * 20 + 8)) * 4;
    const int sm4 = (16 * 8 * 16 + 32 * (8 * 10 * 12 + 8)) * 4;
    cudaFuncSetAttribute(conv1_kernel, cudaFuncAttributeMaxDynamicSharedMemorySize, sm1);
    cudaFuncSetAttribute(c2, cudaFuncAttributeMaxDynamicSharedMemorySize, sm2);
    cudaFuncSetAttribute(c3, cudaFuncAttributeMaxDynamicSharedMemorySize, sm3);
    cudaFuncSetAttribute(c4, cudaFuncAttributeMaxDynamicSharedMemorySize, sm4);

    init_kernel<<<32, 256>>>();
    conv1_kernel<<<1024, 256, sm1>>>(states, conv1_w, conv1_b);
    ln_silu_kernel<32 * 32 * 32, 0><<<1024, 256>>>(ln1_g, ln1_b);
    c2<<<dim3(512, 4), 256, sm2>>>(conv2_w, conv2_b);
    ln_silu_kernel<64 * 16 * 16, 1><<<1024, 256>>>(ln2_g, ln2_b);
    c3<<<dim3(128, 8), 256, sm3>>>(conv3_w, conv3_b);
    ln_silu_kernel<128 * 8 * 8, 2><<<1024, 256>>>(ln3_g, ln3_b);
    c4<<<dim3(32, 16), 256, sm4>>>(conv4_w, conv4_b);
    ln_silu_kernel<256 * 4 * 4, 3><<<1024, 256>>>(ln4_g, ln4_b);
    gemm_kernel<4096, 4096, 0><<<dim3(16, 4), 256>>>(fc_w, fc_b, nullptr, nullptr);           // feats
    gemm_kernel<256, 384, 1><<<dim3(16, 16), 256>>>(post_w + 128, post_b, nullptr, nullptr);  // fpart
    rssm_scan_kernel<<<64, 256>>>(gru_wih, gru_whh, gru_bih, gru_bhh,
                                  post_w, actions, out);
    // prior hoisted out of the scan: prior = h_seq @ prior_w^T + prior_b
    gemm_kernel<128, 128, 2><<<dim3(16, 16), 256>>>(prior_w, prior_b, out + OUT_H, out + OUT_PRIOR);
}